// round 13
// baseline (speedup 1.0000x reference)
#include <cuda_runtime.h>
#include <cuda_bf16.h>
#include <cstdint>

#define NN    10000
#define EE    160000
#define TE    (EE + NN)
#define DIN   768
#define DH    128
#define HEADS 4
#define MP    (2 * NN)           // batched proj rows (x then g)

// ---------------- scratch (static device globals) ----------------
__device__ __align__(256) float         g_xpgp[MP * DH];
__device__ __align__(256) __nv_bfloat16 g_xpgp_hi[MP * DH], g_xpgp_lo[MP * DH];
__device__ __align__(256) float         g_h1pre[NN * HEADS * DH];
__device__ __align__(256) __nv_bfloat16 g_h1_hi[NN * HEADS * DH], g_h1_lo[NN * HEADS * DH];
__device__ __align__(256) float         g_h2pre[NN * DH];
__device__ __align__(256) __nv_bfloat16 g_h2_hi[NN * DH], g_h2_lo[NN * DH];
// transposed + split weights: Bt[n][k]
__device__ __align__(256) __nv_bfloat16 g_wp_hi[DH * DIN],        g_wp_lo[DH * DIN];
__device__ __align__(256) __nv_bfloat16 g_w1_hi[HEADS * DH * DH], g_w1_lo[HEADS * DH * DH];
__device__ __align__(256) __nv_bfloat16 g_w2_hi[DH * HEADS * DH], g_w2_lo[DH * HEADS * DH];
__device__ __align__(256) __nv_bfloat16 g_wd_hi[DIN * DH],        g_wd_lo[DIN * DH];
__device__ float g_as1[NN * HEADS], g_ad1[NN * HEADS], g_as2[NN], g_ad2[NN];
__device__ int   g_deg[NN], g_off[NN + 1], g_cur[NN], g_csr[TE];

// ---------------- helpers ----------------
__device__ __forceinline__ uint32_t smem_u32(const void* p) {
    uint32_t a;
    asm("{ .reg .u64 t; cvta.to.shared.u64 t, %1; cvt.u32.u64 %0, t; }" : "=r"(a) : "l"(p));
    return a;
}
__device__ __forceinline__ void cp16(uint32_t dst, const void* src) {
    asm volatile("cp.async.cg.shared.global [%0], [%1], 16;" :: "r"(dst), "l"(src));
}
#define CP_COMMIT() asm volatile("cp.async.commit_group;" ::: "memory")
#define CP_WAIT1()  asm volatile("cp.async.wait_group 1;" ::: "memory")
#define CP_WAIT0()  asm volatile("cp.async.wait_group 0;" ::: "memory")

__device__ __forceinline__ void mma_bf16(float* c, uint32_t a0, uint32_t a1, uint32_t a2, uint32_t a3,
                                         uint32_t b0, uint32_t b1) {
    asm volatile("mma.sync.aligned.m16n8k16.row.col.f32.bf16.bf16.f32 "
                 "{%0,%1,%2,%3}, {%4,%5,%6,%7}, {%8,%9}, {%0,%1,%2,%3};"
                 : "+f"(c[0]), "+f"(c[1]), "+f"(c[2]), "+f"(c[3])
                 : "r"(a0), "r"(a1), "r"(a2), "r"(a3), "r"(b0), "r"(b1));
}
__device__ __forceinline__ void ldsm4(uint32_t* r, uint32_t addr) {
    asm volatile("ldmatrix.sync.aligned.m8n8.x4.shared.b16 {%0,%1,%2,%3}, [%4];"
                 : "=r"(r[0]), "=r"(r[1]), "=r"(r[2]), "=r"(r[3]) : "r"(addr));
}
__device__ __forceinline__ uint32_t pack_bf2(float a, float b) {
    __nv_bfloat162 p;
    p.x = __float2bfloat16(a);
    p.y = __float2bfloat16(b);
    return *(uint32_t*)&p;
}

// ---------------- fused weight transpose+split (also zeroes g_deg) ----------------
#define WS1 (DIN * DH)
#define WS2 (DH * HEADS * DH)
#define WS3 (HEADS * DH * DH)
#define WS4 (DH * DIN)
__global__ void k_wsplitall(const float* __restrict__ Wp, const float* __restrict__ W1,
                            const float* __restrict__ W2, const float* __restrict__ Wd,
                            __nv_bfloat16* __restrict__ wph, __nv_bfloat16* __restrict__ wpl,
                            __nv_bfloat16* __restrict__ w1h, __nv_bfloat16* __restrict__ w1l,
                            __nv_bfloat16* __restrict__ w2h, __nv_bfloat16* __restrict__ w2l,
                            __nv_bfloat16* __restrict__ wdh, __nv_bfloat16* __restrict__ wdl) {
    int i = blockIdx.x * blockDim.x + threadIdx.x;
    if (i < NN) g_deg[i] = 0;
    const float* W; __nv_bfloat16 *bh, *bl; int K, N, j;
    if (i < WS1)                         { W = Wp; bh = wph; bl = wpl; K = DIN; N = DH;         j = i; }
    else if (i < WS1 + WS2)              { W = W1; bh = w1h; bl = w1l; K = DH;  N = HEADS * DH; j = i - WS1; }
    else if (i < WS1 + WS2 + WS3)        { W = W2; bh = w2h; bl = w2l; K = HEADS * DH; N = DH;  j = i - WS1 - WS2; }
    else if (i < WS1 + WS2 + WS3 + WS4)  { W = Wd; bh = wdh; bl = wdl; K = DH;  N = DIN;        j = i - WS1 - WS2 - WS3; }
    else return;
    int k = j / N, n = j - k * N;
    float v = W[j];
    __nv_bfloat16 h = __float2bfloat16(v);
    bh[(size_t)n * K + k] = h;
    bl[(size_t)n * K + k] = __float2bfloat16(v - __bfloat162float(h));
}

// ---------------- CSR build ----------------
__global__ void k_count(const int* __restrict__ ei) {
    int i = blockIdx.x * blockDim.x + threadIdx.x;
    if (i < EE) atomicAdd(&g_deg[ei[EE + i]], 1);
}
__global__ void k_scan() {
    __shared__ int wsum[32];
    const int CH = 10;
    int tid = threadIdx.x, lane = tid & 31, wid = tid >> 5;
    int base = tid * CH;
    int pref[CH];
    int s = 0;
#pragma unroll
    for (int j = 0; j < CH; j++) {
        int idx = base + j;
        pref[j] = (idx < NN) ? g_deg[idx] + 1 : 0;
        s += pref[j];
    }
    int sc = s;
#pragma unroll
    for (int o = 1; o < 32; o <<= 1) {
        int t = __shfl_up_sync(0xffffffffu, sc, o);
        if (lane >= o) sc += t;
    }
    if (lane == 31) wsum[wid] = sc;
    __syncthreads();
    if (wid == 0) {
        int w = wsum[lane];
#pragma unroll
        for (int o = 1; o < 32; o <<= 1) {
            int t = __shfl_up_sync(0xffffffffu, w, o);
            if (lane >= o) w += t;
        }
        wsum[lane] = w;
    }
    __syncthreads();
    int run = sc - s + (wid ? wsum[wid - 1] : 0);
#pragma unroll
    for (int j = 0; j < CH; j++) {
        int idx = base + j;
        if (idx < NN) { g_off[idx] = run; g_cur[idx] = run; run += pref[j]; }
    }
    if (tid == 1023) g_off[NN] = run;
}
__global__ void k_fill(const int* __restrict__ ei) {
    int i = blockIdx.x * blockDim.x + threadIdx.x;
    if (i < EE) {
        int d = ei[EE + i];
        g_csr[atomicAdd(&g_cur[d], 1)] = ei[i];
    } else if (i < TE) {
        int n = i - EE;
        g_csr[atomicAdd(&g_cur[n], 1)] = n;
    }
}

// ---------------- shared GEMM geometry ----------------
#define RS_B   80
#define B_B    10240
#define BM     64
#define A_B    (BM * RS_B)                 // 5120

// ---------------- general GEMM (2-stage, optional fp32-A in-smem split) ----------------
#define AF_RS  144
#define AF_B   (BM * AF_RS)                // 9216
#define AF_OFF (2 * A_B + 2 * B_B)         // 30720
#define STG    (AF_OFF + AF_B)             // 39936
#define GSMEM  (2 * STG)                   // 79872

__global__ __launch_bounds__(256, 2) void k_gemm_mma(
    const __nv_bfloat16* __restrict__ Ahi, const __nv_bfloat16* __restrict__ Alo,
    const __nv_bfloat16* __restrict__ Bhi, const __nv_bfloat16* __restrict__ Blo,
    const float* __restrict__ bias,
    float* __restrict__ Cf, __nv_bfloat16* __restrict__ Chi, __nv_bfloat16* __restrict__ Clo,
    const float* __restrict__ attS, const float* __restrict__ attD,
    float* __restrict__ outS, float* __restrict__ outD,
    int M, int K, int Nc, int splitRow, int aF32)
{
    constexpr int MT = 2;
    extern __shared__ char smem[];
    const uint32_t sb = smem_u32(smem);
    const int tid = threadIdx.x, wid = tid >> 5, lane = tid & 31;
    const int gid = lane >> 2, tig = lane & 3;
    const int mBase = blockIdx.y * BM, nBase = blockIdx.x * 128;
    const int wrow = (wid & 1) * 32, wcol = (wid >> 1) * 32;

    float acc[MT][4][4];
#pragma unroll
    for (int i = 0; i < MT; i++)
#pragma unroll
        for (int j = 0; j < 4; j++)
#pragma unroll
            for (int q = 0; q < 4; q++) acc[i][j][q] = 0.f;

    const int nchunk = K >> 5;
    const uint32_t aOff = (uint32_t)((wrow + (lane & 15)) * RS_B + (lane >> 4) * 16);
    const uint32_t bOff = (uint32_t)(2 * A_B + (wcol + ((lane >> 4) << 3) + (lane & 7)) * RS_B
                                     + ((lane >> 3) & 1) * 16);

    auto fill = [&](uint32_t bufbase, int k0) {
        if (aF32) {
#pragma unroll
            for (int i = tid; i < 512; i += 256) {
                int row = i >> 3, seg = i & 7;
                uint32_t so = AF_OFF + (uint32_t)(row * AF_RS + seg * 16);
                int ra = mBase + row; if (ra > M - 1) ra = M - 1;
                const float* src = (ra < splitRow)
                    ? ((const float*)Ahi + (size_t)ra * K)
                    : ((const float*)Alo + (size_t)(ra - splitRow) * K);
                cp16(bufbase + so, src + k0 + seg * 4);
            }
        } else {
            int row = tid >> 2, seg = tid & 3;
            uint32_t so = (uint32_t)(row * RS_B + seg * 16);
            int ra = mBase + row; if (ra > M - 1) ra = M - 1;
            size_t ea = (size_t)ra * K + k0 + seg * 8;
            cp16(bufbase + so,       Ahi + ea);
            cp16(bufbase + A_B + so, Alo + ea);
        }
#pragma unroll
        for (int i = tid; i < 512; i += 256) {
            int row = i >> 2, seg = i & 3;
            uint32_t so = (uint32_t)(row * RS_B + seg * 16);
            size_t eb = (size_t)(nBase + row) * K + k0 + seg * 8;
            cp16(bufbase + 2 * A_B + so,       Bhi + eb);
            cp16(bufbase + 2 * A_B + B_B + so, Blo + eb);
        }
    };

    fill(sb, 0);
    CP_COMMIT();

    for (int c = 0; c < nchunk; c++) {
        if (c + 1 < nchunk) {
            fill(sb + ((c + 1) & 1) * STG, (c + 1) << 5);
            CP_COMMIT();
            CP_WAIT1();
        } else {
            CP_WAIT0();
        }
        __syncthreads();

        const uint32_t rel = (uint32_t)(c & 1) * STG;
        if (aF32) {
            int row = tid >> 2, g4 = tid & 3;
            const char* fp = smem + rel + AF_OFF + row * AF_RS + g4 * 32;
            float4 va = *(const float4*)fp;
            float4 vb = *(const float4*)(fp + 16);
            uint32_t hi[4], lo[4];
            hi[0] = pack_bf2(va.x, va.y);
            hi[1] = pack_bf2(va.z, va.w);
            hi[2] = pack_bf2(vb.x, vb.y);
            hi[3] = pack_bf2(vb.z, vb.w);
            lo[0] = pack_bf2(va.x - __bfloat162float(((__nv_bfloat162*)&hi[0])->x),
                             va.y - __bfloat162float(((__nv_bfloat162*)&hi[0])->y));
            lo[1] = pack_bf2(va.z - __bfloat162float(((__nv_bfloat162*)&hi[1])->x),
                             va.w - __bfloat162float(((__nv_bfloat162*)&hi[1])->y));
            lo[2] = pack_bf2(vb.x - __bfloat162float(((__nv_bfloat162*)&hi[2])->x),
                             vb.y - __bfloat162float(((__nv_bfloat162*)&hi[2])->y));
            lo[3] = pack_bf2(vb.z - __bfloat162float(((__nv_bfloat162*)&hi[3])->x),
                             vb.w - __bfloat162float(((__nv_bfloat162*)&hi[3])->y));
            *(uint4*)(smem + rel + row * RS_B + g4 * 16)       = make_uint4(hi[0], hi[1], hi[2], hi[3]);
            *(uint4*)(smem + rel + A_B + row * RS_B + g4 * 16) = make_uint4(lo[0], lo[1], lo[2], lo[3]);
            __syncthreads();
        }

        const uint32_t sbuf = sb + rel;
        const uint32_t aB = sbuf + aOff;
        const uint32_t bB = sbuf + bOff;

#pragma unroll
        for (int ks = 0; ks < 2; ks++) {
            const uint32_t ko = ks * 32;
            uint32_t ah[MT][4], al[MT][4], bh[4][2], bl[4][2];
#pragma unroll
            for (int mt = 0; mt < MT; mt++) {
                ldsm4(ah[mt], aB + mt * (16 * RS_B) + ko);
                ldsm4(al[mt], aB + A_B + mt * (16 * RS_B) + ko);
            }
#pragma unroll
            for (int p = 0; p < 2; p++) {
                uint32_t r[4];
                ldsm4(r, bB + p * (16 * RS_B) + ko);
                bh[2 * p][0] = r[0]; bh[2 * p][1] = r[1];
                bh[2 * p + 1][0] = r[2]; bh[2 * p + 1][1] = r[3];
                ldsm4(r, bB + B_B + p * (16 * RS_B) + ko);
                bl[2 * p][0] = r[0]; bl[2 * p][1] = r[1];
                bl[2 * p + 1][0] = r[2]; bl[2 * p + 1][1] = r[3];
            }
#pragma unroll
            for (int mt = 0; mt < MT; mt++)
#pragma unroll
                for (int nt = 0; nt < 4; nt++) {
                    mma_bf16(acc[mt][nt], ah[mt][0], ah[mt][1], ah[mt][2], ah[mt][3], bh[nt][0], bh[nt][1]);
                    mma_bf16(acc[mt][nt], ah[mt][0], ah[mt][1], ah[mt][2], ah[mt][3], bl[nt][0], bl[nt][1]);
                    mma_bf16(acc[mt][nt], al[mt][0], al[mt][1], al[mt][2], al[mt][3], bh[nt][0], bh[nt][1]);
                }
        }
        __syncthreads();
    }

    // epilogue (+ optional fused attention dot partials)
    float* sA = (float*)smem;
    float* sD = sA + 4 * BM;
    const int hh = blockIdx.x;

#pragma unroll
    for (int mt = 0; mt < MT; mt++) {
#pragma unroll
        for (int half = 0; half < 2; half++) {
            const int lrow = wrow + mt * 16 + gid + half * 8;
            const int row = mBase + lrow;
            float ps = 0.f, pd = 0.f;
#pragma unroll
            for (int nt = 0; nt < 4; nt++) {
                const int cl = wcol + nt * 8 + tig * 2;
                const int col = nBase + cl;
                float v0 = acc[mt][nt][half * 2 + 0];
                float v1 = acc[mt][nt][half * 2 + 1];
                if (bias) { v0 += bias[col]; v1 += bias[col + 1]; }
                if (attS) {
                    ps += v0 * attS[hh * 128 + cl] + v1 * attS[hh * 128 + cl + 1];
                    pd += v0 * attD[hh * 128 + cl] + v1 * attD[hh * 128 + cl + 1];
                }
                if (row < M) {
                    size_t oi = (size_t)row * Nc + col;
                    if (Cf && row >= splitRow) *(float2*)(Cf + oi) = make_float2(v0, v1);
                    if (Chi && row < splitRow) {
                        __nv_bfloat162 h, l;
                        h.x = __float2bfloat16(v0); l.x = __float2bfloat16(v0 - __bfloat162float(h.x));
                        h.y = __float2bfloat16(v1); l.y = __float2bfloat16(v1 - __bfloat162float(h.y));
                        *(__nv_bfloat162*)(Chi + oi) = h;
                        *(__nv_bfloat162*)(Clo + oi) = l;
                    }
                }
            }
            if (attS) {
                ps += __shfl_xor_sync(0xffffffffu, ps, 1);
                ps += __shfl_xor_sync(0xffffffffu, ps, 2);
                pd += __shfl_xor_sync(0xffffffffu, pd, 1);
                pd += __shfl_xor_sync(0xffffffffu, pd, 2);
                if (tig == 0) {
                    sA[(wid >> 1) * BM + lrow] = ps;
                    sD[(wid >> 1) * BM + lrow] = pd;
                }
            }
        }
    }
    if (attS) {
        __syncthreads();
        if (tid < BM) {
            int row = mBase + tid;
            if (row < M) {
                int H = Nc >> 7;
                outS[row * H + hh] = sA[tid] + sA[BM + tid] + sA[2 * BM + tid] + sA[3 * BM + tid];
                outD[row * H + hh] = sD[tid] + sD[BM + tid] + sD[2 * BM + tid] + sD[3 * BM + tid];
            }
        }
    }
}

// ---------------- K=128 A-resident multi-N GEMM (gat1 lin, decoder) ----------------
// A (all 4 k-chunks, hi+lo) resident in smem; loop over NB column blocks streaming B only.
#define KR_A_CH  (2 * A_B)                 // 10240 per chunk (Ah then Al)
#define KR_A_TOT (4 * KR_A_CH)             // 40960
#define KR_B_STG (2 * B_B)                 // 20480
#define KR_SRED  (KR_A_TOT + 2 * KR_B_STG) // 81920
#define KR_SMEM  (KR_SRED + 8 * BM * 4)    // 83968

__global__ __launch_bounds__(256, 2) void k_gemm_kres(
    const __nv_bfloat16* __restrict__ Ahi, const __nv_bfloat16* __restrict__ Alo,
    const __nv_bfloat16* __restrict__ Bhi, const __nv_bfloat16* __restrict__ Blo,
    const float* __restrict__ bias,
    float* __restrict__ Cf,
    const float* __restrict__ attS, const float* __restrict__ attD,
    float* __restrict__ outS, float* __restrict__ outD,
    int M, int NB, int Nc)
{
    constexpr int MT = 2;
    const int K = 128;
    extern __shared__ char smem[];
    const uint32_t sb = smem_u32(smem);
    const int tid = threadIdx.x, wid = tid >> 5, lane = tid & 31;
    const int gid = lane >> 2, tig = lane & 3;
    const int mBase = blockIdx.y * BM;
    const int wrow = (wid & 1) * 32, wcol = (wid >> 1) * 32;

    const uint32_t aOff = (uint32_t)((wrow + (lane & 15)) * RS_B + (lane >> 4) * 16);
    const uint32_t bOffB = (uint32_t)((wcol + ((lane >> 4) << 3) + (lane & 7)) * RS_B
                                      + ((lane >> 3) & 1) * 16);

    // load full A (4 chunks x (Ah,Al))
    {
        int row = tid >> 2, seg = tid & 3;
        int ra = mBase + row; if (ra > M - 1) ra = M - 1;
        const size_t abase = (size_t)ra * K;
        uint32_t so = (uint32_t)(row * RS_B + seg * 16);
#pragma unroll
        for (int ch = 0; ch < 4; ch++) {
            size_t ea = abase + ch * 32 + seg * 8;
            cp16(sb + ch * KR_A_CH + so,       Ahi + ea);
            cp16(sb + ch * KR_A_CH + A_B + so, Alo + ea);
        }
    }

    auto fillB = [&](int stage, int it) {
        int nb = it >> 2, c = it & 3;
        uint32_t base = sb + KR_A_TOT + (uint32_t)stage * KR_B_STG;
#pragma unroll
        for (int i = tid; i < 512; i += 256) {
            int row = i >> 2, seg = i & 3;
            uint32_t so = (uint32_t)(row * RS_B + seg * 16);
            size_t eb = (size_t)(nb * 128 + row) * K + c * 32 + seg * 8;
            cp16(base + so,       Bhi + eb);
            cp16(base + B_B + so, Blo + eb);
        }
    };

    fillB(0, 0);
    CP_COMMIT();

    float acc[MT][4][4];
    float* sA = (float*)(smem + KR_SRED);
    float* sD = sA + 4 * BM;
    const int nit = NB * 4;

    for (int it = 0; it < nit; it++) {
        if (it + 1 < nit) {
            fillB((it + 1) & 1, it + 1);
            CP_COMMIT();
            CP_WAIT1();
        } else {
            CP_WAIT0();
        }
        __syncthreads();

        const int c = it & 3, nb = it >> 2;
        if (c == 0) {
#pragma unroll
            for (int i = 0; i < MT; i++)
#pragma unroll
                for (int j = 0; j < 4; j++)
#pragma unroll
                    for (int q = 0; q < 4; q++) acc[i][j][q] = 0.f;
        }

        const uint32_t aB = sb + c * KR_A_CH + aOff;
        const uint32_t bB = sb + KR_A_TOT + (uint32_t)(it & 1) * KR_B_STG + bOffB;

#pragma unroll
        for (int ks = 0; ks < 2; ks++) {
            const uint32_t ko = ks * 32;
            uint32_t ah[MT][4], al[MT][4], bh[4][2], bl[4][2];
#pragma unroll
            for (int mt = 0; mt < MT; mt++) {
                ldsm4(ah[mt], aB + mt * (16 * RS_B) + ko);
                ldsm4(al[mt], aB + A_B + mt * (16 * RS_B) + ko);
            }
#pragma unroll
            for (int p = 0; p < 2; p++) {
                uint32_t r[4];
                ldsm4(r, bB + p * (16 * RS_B) + ko);
                bh[2 * p][0] = r[0]; bh[2 * p][1] = r[1];
                bh[2 * p + 1][0] = r[2]; bh[2 * p + 1][1] = r[3];
                ldsm4(r, bB + B_B + p * (16 * RS_B) + ko);
                bl[2 * p][0] = r[0]; bl[2 * p][1] = r[1];
                bl[2 * p + 1][0] = r[2]; bl[2 * p + 1][1] = r[3];
            }
#pragma unroll
            for (int mt = 0; mt < MT; mt++)
#pragma unroll
                for (int nt = 0; nt < 4; nt++) {
                    mma_bf16(acc[mt][nt], ah[mt][0], ah[mt][1], ah[mt][2], ah[mt][3], bh[nt][0], bh[nt][1]);
                    mma_bf16(acc[mt][nt], ah[mt][0], ah[mt][1], ah[mt][2], ah[mt][3], bl[nt][0], bl[nt][1]);
                    mma_bf16(acc[mt][nt], al[mt][0], al[mt][1], al[mt][2], al[mt][3], bh[nt][0], bh[nt][1]);
                }
        }

        if (c == 3) {
            // epilogue for column block nb
            const int nBase = nb * 128;
#pragma unroll
            for (int mt = 0; mt < MT; mt++) {
#pragma unroll
                for (int half = 0; half < 2; half++) {
                    const int lrow = wrow + mt * 16 + gid + half * 8;
                    const int row = mBase + lrow;
                    float ps = 0.f, pd = 0.f;
#pragma unroll
                    for (int nt = 0; nt < 4; nt++) {
                        const int cl = wcol + nt * 8 + tig * 2;
                        const int col = nBase + cl;
                        float v0 = acc[mt][nt][half * 2 + 0];
                        float v1 = acc[mt][nt][half * 2 + 1];
                        if (bias) { v0 += bias[col]; v1 += bias[col + 1]; }
                        if (attS) {
                            ps += v0 * attS[nb * 128 + cl] + v1 * attS[nb * 128 + cl + 1];
                            pd += v0 * attD[nb * 128 + cl] + v1 * attD[nb * 128 + cl + 1];
                        }
                        if (row < M)
                            *(float2*)(Cf + (size_t)row * Nc + col) = make_float2(v0, v1);
                    }
                    if (attS) {
                        ps += __shfl_xor_sync(0xffffffffu, ps, 1);
                        ps += __shfl_xor_sync(0xffffffffu, ps, 2);
                        pd += __shfl_xor_sync(0xffffffffu, pd, 1);
                        pd += __shfl_xor_sync(0xffffffffu, pd, 2);
                        if (tig == 0) {
                            sA[(wid >> 1) * BM + lrow] = ps;
                            sD[(wid >> 1) * BM + lrow] = pd;
                        }
                    }
                }
            }
            if (attS) {
                __syncthreads();
                if (tid < BM) {
                    int row = mBase + tid;
                    if (row < M) {
                        outS[row * NB + nb] = sA[tid] + sA[BM + tid] + sA[2 * BM + tid] + sA[3 * BM + tid];
                        outD[row * NB + nb] = sD[tid] + sD[BM + tid] + sD[2 * BM + tid] + sD[3 * BM + tid];
                    }
                }
            }
        }
        __syncthreads();
    }
}

__device__ __forceinline__ float lrelu(float e) { return e > 0.f ? e : 0.2f * e; }

// ---------------- GAT1 agg: single-pass softmax + bias + ELU + bf16 split out ----------------
__global__ void k_agg1(const float* __restrict__ hpre, const float* __restrict__ as_,
                       const float* __restrict__ ad_, const float* __restrict__ bias,
                       __nv_bfloat16* __restrict__ ohi, __nv_bfloat16* __restrict__ olo) {
    int gw = (blockIdx.x * blockDim.x + threadIdx.x) >> 5;
    int lane = threadIdx.x & 31;
    if (gw >= NN * HEADS) return;
    int n = gw / HEADS, hh = gw - n * HEADS;
    int beg = g_off[n], end = g_off[n + 1];
    float adn = ad_[gw];

    float ws = 0.f;
    float4 acc = make_float4(0.f, 0.f, 0.f, 0.f);
    const float4* h4 = (const float4*)hpre;
    for (int i = beg; i < end; i++) {
        int s = g_csr[i];
        float ex = __expf(lrelu(as_[s * HEADS + hh] + adn));
        ws += ex;
        float4 v = h4[(size_t)(s * HEADS + hh) * 32 + lane];
        acc.x += ex * v.x; acc.y += ex * v.y; acc.z += ex * v.z; acc.w += ex * v.w;
    }
    float inv = 1.f / (ws + 1e-16f);
    float4 b = ((const float4*)bias)[hh * 32 + lane];
    float4 o;
    o.x = acc.x * inv + b.x; o.y = acc.y * inv + b.y;
    o.z = acc.z * inv + b.z; o.w = acc.w * inv + b.w;
    o.x = o.x > 0.f ? o.x : expm1f(o.x);
    o.y = o.y > 0.f ? o.y : expm1f(o.y);
    o.z = o.z > 0.f ? o.z : expm1f(o.z);
    o.w = o.w > 0.f ? o.w : expm1f(o.w);
    size_t oi = (size_t)gw * 128 + lane * 4;
    __nv_bfloat162 h01, h23, l01, l23;
    h01.x = __float2bfloat16(o.x); l01.x = __float2bfloat16(o.x - __bfloat162float(h01.x));
    h01.y = __float2bfloat16(o.y); l01.y = __float2bfloat16(o.y - __bfloat162float(h01.y));
    h23.x = __float2bfloat16(o.z); l23.x = __float2bfloat16(o.z - __bfloat162float(h23.x));
    h23.y = __float2bfloat16(o.w); l23.y = __float2bfloat16(o.w - __bfloat162float(h23.y));
    *(__nv_bfloat162*)(ohi + oi) = h01; *(__nv_bfloat162*)(ohi + oi + 2) = h23;
    *(__nv_bfloat162*)(olo + oi) = l01; *(__nv_bfloat162*)(olo + oi + 2) = l23;
}

// ---------------- GAT2 agg: single-pass softmax + bias + beta*gp + bf16 split out ----------------
__global__ void k_agg2(const float* __restrict__ hpre, const float* __restrict__ as_,
                       const float* __restrict__ ad_, const float* __restrict__ bias,
                       const float* __restrict__ gp, const float* __restrict__ beta,
                       __nv_bfloat16* __restrict__ ohi, __nv_bfloat16* __restrict__ olo) {
    int n = (blockIdx.x * blockDim.x + threadIdx.x) >> 5;
    int lane = threadIdx.x & 31;
    if (n >= NN) return;
    int beg = g_off[n], end = g_off[n + 1];
    float adn = ad_[n];

    float ws = 0.f;
    float4 acc = make_float4(0.f, 0.f, 0.f, 0.f);
    const float4* h4 = (const float4*)hpre;
    for (int i = beg; i < end; i++) {
        int s = g_csr[i];
        float ex = __expf(lrelu(as_[s] + adn));
        ws += ex;
        float4 v = h4[(size_t)s * 32 + lane];
        acc.x += ex * v.x; acc.y += ex * v.y; acc.z += ex * v.z; acc.w += ex * v.w;
    }
    float inv = 1.f / (ws + 1e-16f);
    float bt = *beta;
    float4 b = ((const float4*)bias)[lane];
    float4 gv = ((const float4*)gp)[(size_t)n * 32 + lane];
    float4 o;
    o.x = acc.x * inv + b.x + bt * gv.x;
    o.y = acc.y * inv + b.y + bt * gv.y;
    o.z = acc.z * inv + b.z + bt * gv.z;
    o.w = acc.w * inv + b.w + bt * gv.w;
    size_t oi = (size_t)n * 128 + lane * 4;
    __nv_bfloat162 h01, h23, l01, l23;
    h01.x = __float2bfloat16(o.x); l01.x = __float2bfloat16(o.x - __bfloat162float(h01.x));
    h01.y = __float2bfloat16(o.y); l01.y = __float2bfloat16(o.y - __bfloat162float(h01.y));
    h23.x = __float2bfloat16(o.z); l23.x = __float2bfloat16(o.z - __bfloat162float(h23.x));
    h23.y = __float2bfloat16(o.w); l23.y = __float2bfloat16(o.w - __bfloat162float(h23.y));
    *(__nv_bfloat162*)(ohi + oi) = h01; *(__nv_bfloat162*)(ohi + oi + 2) = h23;
    *(__nv_bfloat162*)(olo + oi) = l01; *(__nv_bfloat162*)(olo + oi + 2) = l23;
}

// ---------------- launch ----------------
extern "C" void kernel_launch(void* const* d_in, const int* in_sizes, int n_in,
                              void* d_out, int out_size) {
    const float* x      = (const float*)d_in[0];
    const int*   ei     = (const int*)  d_in[1];
    const float* g      = (const float*)d_in[2];
    const float* proj_W = (const float*)d_in[3];
    const float* proj_b = (const float*)d_in[4];
    const float* g1_W   = (const float*)d_in[5];
    const float* g1_as  = (const float*)d_in[6];
    const float* g1_ad  = (const float*)d_in[7];
    const float* g1_b   = (const float*)d_in[8];
    const float* g2_W   = (const float*)d_in[9];
    const float* g2_as  = (const float*)d_in[10];
    const float* g2_ad  = (const float*)d_in[11];
    const float* g2_b   = (const float*)d_in[12];
    const float* dec_W  = (const float*)d_in[13];
    const float* dec_b  = (const float*)d_in[14];
    const float* beta   = (const float*)d_in[15];
    float* out = (float*)d_out;

    __nv_bfloat16 *xpgp_hi, *xpgp_lo, *h1_hi, *h1_lo, *h2_hi, *h2_lo;
    __nv_bfloat16 *wp_hi, *wp_lo, *w1_hi, *w1_lo, *w2_hi, *w2_lo, *wd_hi, *wd_lo;
    float *xpgp, *h1pre, *h2pre, *as1, *ad1, *as2, *ad2;
    cudaGetSymbolAddress((void**)&xpgp,    g_xpgp);
    cudaGetSymbolAddress((void**)&xpgp_hi, g_xpgp_hi); cudaGetSymbolAddress((void**)&xpgp_lo, g_xpgp_lo);
    cudaGetSymbolAddress((void**)&h1pre,   g_h1pre);
    cudaGetSymbolAddress((void**)&h1_hi,   g_h1_hi);   cudaGetSymbolAddress((void**)&h1_lo,   g_h1_lo);
    cudaGetSymbolAddress((void**)&h2pre,   g_h2pre);
    cudaGetSymbolAddress((void**)&h2_hi,   g_h2_hi);   cudaGetSymbolAddress((void**)&h2_lo,   g_h2_lo);
    cudaGetSymbolAddress((void**)&wp_hi,   g_wp_hi);   cudaGetSymbolAddress((void**)&wp_lo,   g_wp_lo);
    cudaGetSymbolAddress((void**)&w1_hi,   g_w1_hi);   cudaGetSymbolAddress((void**)&w1_lo,   g_w1_lo);
    cudaGetSymbolAddress((void**)&w2_hi,   g_w2_hi);   cudaGetSymbolAddress((void**)&w2_lo,   g_w2_lo);
    cudaGetSymbolAddress((void**)&wd_hi,   g_wd_hi);   cudaGetSymbolAddress((void**)&wd_lo,   g_wd_lo);
    cudaGetSymbolAddress((void**)&as1, g_as1); cudaGetSymbolAddress((void**)&ad1, g_ad1);
    cudaGetSymbolAddress((void**)&as2, g_as2); cudaGetSymbolAddress((void**)&ad2, g_ad2);

    cudaFuncSetAttribute(k_gemm_mma, cudaFuncAttributeMaxDynamicSharedMemorySize, GSMEM);
    cudaFuncSetAttribute(k_gemm_kres, cudaFuncAttributeMaxDynamicSharedMemorySize, KR_SMEM);

    // prep: weight split (+deg zero) -> count -> scan -> fill
    k_wsplitall<<<(WS1 + WS2 + WS3 + WS4 + 255) / 256, 256>>>(
        proj_W, g1_W, g2_W, dec_W, wp_hi, wp_lo, w1_hi, w1_lo, w2_hi, w2_lo, wd_hi, wd_lo);
    k_count<<<(EE + 255) / 256, 256>>>(ei);
    k_scan<<<1, 1024>>>();
    k_fill<<<(TE + 255) / 256, 256>>>(ei);

    // proj (batched x|g, fp32 A direct): rows<NN -> hi/lo (GAT1 input), rows>=NN -> f32 (gp)
    k_gemm_mma<<<dim3(1, (MP + BM - 1) / BM), 256, GSMEM>>>(
        (const __nv_bfloat16*)x, (const __nv_bfloat16*)g, wp_hi, wp_lo, proj_b,
        xpgp, xpgp_hi, xpgp_lo,
        nullptr, nullptr, nullptr, nullptr, MP, DIN, DH, NN, 1);

    // GAT1: [10000,128] @ [128,512], A-resident over 4 column blocks + fused attn dots
    k_gemm_kres<<<dim3(1, (NN + BM - 1) / BM), 256, KR_SMEM>>>(
        xpgp_hi, xpgp_lo, w1_hi, w1_lo, nullptr, h1pre,
        g1_as, g1_ad, as1, ad1, NN, HEADS, HEADS * DH);
    k_agg1<<<(NN * HEADS * 32 + 255) / 256, 256>>>(h1pre, as1, ad1, g1_b, h1_hi, h1_lo);

    // GAT2: [10000,512] @ [512,128] + fused attention dots
    k_gemm_mma<<<dim3(1, (NN + BM - 1) / BM), 256, GSMEM>>>(
        h1_hi, h1_lo, w2_hi, w2_lo, nullptr, h2pre, nullptr, nullptr,
        g2_as, g2_ad, as2, ad2, NN, HEADS * DH, DH, 0, 0);
    k_agg2<<<(NN * 32 + 255) / 256, 256>>>(h2pre, as2, ad2, g2_b, xpgp + (size_t)NN * DH, beta, h2_hi, h2_lo);

    // decoder: [10000,128] @ [128,768], A-resident over 6 column blocks
    k_gemm_kres<<<dim3(1, (NN + BM - 1) / BM), 256, KR_SMEM>>>(
        h2_hi, h2_lo, wd_hi, wd_lo, dec_b, out,
        nullptr, nullptr, nullptr, nullptr, NN, DIN / 128, DIN);
}

// round 14
// speedup vs baseline: 1.1200x; 1.1200x over previous
#include <cuda_runtime.h>
#include <cuda_bf16.h>
#include <cstdint>

#define NN    10000
#define EE    160000
#define TE    (EE + NN)
#define DIN   768
#define DH    128
#define HEADS 4
#define MP    (2 * NN)           // batched proj rows (x then g)

// ---------------- scratch (static device globals) ----------------
__device__ __align__(256) float         g_xpgp[MP * DH];
__device__ __align__(256) __nv_bfloat16 g_xpgp_hi[MP * DH], g_xpgp_lo[MP * DH];
__device__ __align__(256) float         g_h1pre[NN * HEADS * DH];
__device__ __align__(256) __nv_bfloat16 g_h1_hi[NN * HEADS * DH], g_h1_lo[NN * HEADS * DH];
__device__ __align__(256) float         g_h2pre[NN * DH];
__device__ __align__(256) __nv_bfloat16 g_h2_hi[NN * DH], g_h2_lo[NN * DH];
// transposed + split weights: Bt[n][k]
__device__ __align__(256) __nv_bfloat16 g_wp_hi[DH * DIN],        g_wp_lo[DH * DIN];
__device__ __align__(256) __nv_bfloat16 g_w1_hi[HEADS * DH * DH], g_w1_lo[HEADS * DH * DH];
__device__ __align__(256) __nv_bfloat16 g_w2_hi[DH * HEADS * DH], g_w2_lo[DH * HEADS * DH];
__device__ __align__(256) __nv_bfloat16 g_wd_hi[DIN * DH],        g_wd_lo[DIN * DH];
__device__ float g_as1[NN * HEADS], g_ad1[NN * HEADS], g_as2[NN], g_ad2[NN];
__device__ int   g_deg[NN], g_off[NN + 1], g_cur[NN], g_csr[TE];

// ---------------- helpers ----------------
__device__ __forceinline__ uint32_t smem_u32(const void* p) {
    uint32_t a;
    asm("{ .reg .u64 t; cvta.to.shared.u64 t, %1; cvt.u32.u64 %0, t; }" : "=r"(a) : "l"(p));
    return a;
}
__device__ __forceinline__ void cp16(uint32_t dst, const void* src) {
    asm volatile("cp.async.cg.shared.global [%0], [%1], 16;" :: "r"(dst), "l"(src));
}
#define CP_COMMIT() asm volatile("cp.async.commit_group;" ::: "memory")
#define CP_WAIT1()  asm volatile("cp.async.wait_group 1;" ::: "memory")
#define CP_WAIT0()  asm volatile("cp.async.wait_group 0;" ::: "memory")

__device__ __forceinline__ void mma_bf16(float* c, uint32_t a0, uint32_t a1, uint32_t a2, uint32_t a3,
                                         uint32_t b0, uint32_t b1) {
    asm volatile("mma.sync.aligned.m16n8k16.row.col.f32.bf16.bf16.f32 "
                 "{%0,%1,%2,%3}, {%4,%5,%6,%7}, {%8,%9}, {%0,%1,%2,%3};"
                 : "+f"(c[0]), "+f"(c[1]), "+f"(c[2]), "+f"(c[3])
                 : "r"(a0), "r"(a1), "r"(a2), "r"(a3), "r"(b0), "r"(b1));
}
__device__ __forceinline__ void ldsm4(uint32_t* r, uint32_t addr) {
    asm volatile("ldmatrix.sync.aligned.m8n8.x4.shared.b16 {%0,%1,%2,%3}, [%4];"
                 : "=r"(r[0]), "=r"(r[1]), "=r"(r[2]), "=r"(r[3]) : "r"(addr));
}
__device__ __forceinline__ uint32_t pack_bf2(float a, float b) {
    __nv_bfloat162 p;
    p.x = __float2bfloat16(a);
    p.y = __float2bfloat16(b);
    return *(uint32_t*)&p;
}

// ---------------- fused weight transpose+split + edge degree count ----------------
// g_deg zeroed by cudaMemsetAsync BEFORE this kernel.
#define WS1 (DIN * DH)
#define WS2 (DH * HEADS * DH)
#define WS3 (HEADS * DH * DH)
#define WS4 (DH * DIN)
__global__ void k_wsplitall(const float* __restrict__ Wp, const float* __restrict__ W1,
                            const float* __restrict__ W2, const float* __restrict__ Wd,
                            const int* __restrict__ ei,
                            __nv_bfloat16* __restrict__ wph, __nv_bfloat16* __restrict__ wpl,
                            __nv_bfloat16* __restrict__ w1h, __nv_bfloat16* __restrict__ w1l,
                            __nv_bfloat16* __restrict__ w2h, __nv_bfloat16* __restrict__ w2l,
                            __nv_bfloat16* __restrict__ wdh, __nv_bfloat16* __restrict__ wdl) {
    int i = blockIdx.x * blockDim.x + threadIdx.x;
    if (i < EE) atomicAdd(&g_deg[ei[EE + i]], 1);
    const float* W; __nv_bfloat16 *bh, *bl; int K, N, j;
    if (i < WS1)                         { W = Wp; bh = wph; bl = wpl; K = DIN; N = DH;         j = i; }
    else if (i < WS1 + WS2)              { W = W1; bh = w1h; bl = w1l; K = DH;  N = HEADS * DH; j = i - WS1; }
    else if (i < WS1 + WS2 + WS3)        { W = W2; bh = w2h; bl = w2l; K = HEADS * DH; N = DH;  j = i - WS1 - WS2; }
    else if (i < WS1 + WS2 + WS3 + WS4)  { W = Wd; bh = wdh; bl = wdl; K = DH;  N = DIN;        j = i - WS1 - WS2 - WS3; }
    else return;
    int k = j / N, n = j - k * N;
    float v = W[j];
    __nv_bfloat16 h = __float2bfloat16(v);
    bh[(size_t)n * K + k] = h;
    bl[(size_t)n * K + k] = __float2bfloat16(v - __bfloat162float(h));
}

// ---------------- CSR scan + fill ----------------
__global__ void k_scan() {
    __shared__ int wsum[32];
    const int CH = 10;
    int tid = threadIdx.x, lane = tid & 31, wid = tid >> 5;
    int base = tid * CH;
    int pref[CH];
    int s = 0;
#pragma unroll
    for (int j = 0; j < CH; j++) {
        int idx = base + j;
        pref[j] = (idx < NN) ? g_deg[idx] + 1 : 0;
        s += pref[j];
    }
    int sc = s;
#pragma unroll
    for (int o = 1; o < 32; o <<= 1) {
        int t = __shfl_up_sync(0xffffffffu, sc, o);
        if (lane >= o) sc += t;
    }
    if (lane == 31) wsum[wid] = sc;
    __syncthreads();
    if (wid == 0) {
        int w = wsum[lane];
#pragma unroll
        for (int o = 1; o < 32; o <<= 1) {
            int t = __shfl_up_sync(0xffffffffu, w, o);
            if (lane >= o) w += t;
        }
        wsum[lane] = w;
    }
    __syncthreads();
    int run = sc - s + (wid ? wsum[wid - 1] : 0);
#pragma unroll
    for (int j = 0; j < CH; j++) {
        int idx = base + j;
        if (idx < NN) { g_off[idx] = run; g_cur[idx] = run; run += pref[j]; }
    }
    if (tid == 1023) g_off[NN] = run;
}
__global__ void k_fill(const int* __restrict__ ei) {
    int i = blockIdx.x * blockDim.x + threadIdx.x;
    if (i < EE) {
        int d = ei[EE + i];
        g_csr[atomicAdd(&g_cur[d], 1)] = ei[i];
    } else if (i < TE) {
        int n = i - EE;
        g_csr[atomicAdd(&g_cur[n], 1)] = n;
    }
}

// ---------------- mma.sync bf16x3 GEMM (BM=64, occ 2, 2-stage) ----------------
// aF32=0: A pre-split bf16 (Ahi/Alo). aF32=1: Ahi=x(f32), Alo=g(f32), rows>=splitRow from g;
// fp32 tile staged at AF_OFF (144 B rows), converted in-smem to the same Ah/Al layout.
#define RS_B   80
#define B_B    10240
#define BM     64
#define A_B    (BM * RS_B)                 // 5120
#define AF_RS  144
#define AF_B   (BM * AF_RS)                // 9216
#define AF_OFF (2 * A_B + 2 * B_B)         // 30720
#define STG    (AF_OFF + AF_B)             // 39936
#define GSMEM  (2 * STG)                   // 79872

__global__ __launch_bounds__(256, 2) void k_gemm_mma(
    const __nv_bfloat16* __restrict__ Ahi, const __nv_bfloat16* __restrict__ Alo,
    const __nv_bfloat16* __restrict__ Bhi, const __nv_bfloat16* __restrict__ Blo,
    const float* __restrict__ bias,
    float* __restrict__ Cf, __nv_bfloat16* __restrict__ Chi, __nv_bfloat16* __restrict__ Clo,
    const float* __restrict__ attS, const float* __restrict__ attD,
    float* __restrict__ outS, float* __restrict__ outD,
    int M, int K, int Nc, int splitRow, int aF32)
{
    constexpr int MT = 2;
    extern __shared__ char smem[];
    const uint32_t sb = smem_u32(smem);
    const int tid = threadIdx.x, wid = tid >> 5, lane = tid & 31;
    const int gid = lane >> 2, tig = lane & 3;
    const int mBase = blockIdx.y * BM, nBase = blockIdx.x * 128;
    const int wrow = (wid & 1) * 32, wcol = (wid >> 1) * 32;

    float acc[MT][4][4];
#pragma unroll
    for (int i = 0; i < MT; i++)
#pragma unroll
        for (int j = 0; j < 4; j++)
#pragma unroll
            for (int q = 0; q < 4; q++) acc[i][j][q] = 0.f;

    const int nchunk = K >> 5;
    const uint32_t aOff = (uint32_t)((wrow + (lane & 15)) * RS_B + (lane >> 4) * 16);
    const uint32_t bOff = (uint32_t)(2 * A_B + (wcol + ((lane >> 4) << 3) + (lane & 7)) * RS_B
                                     + ((lane >> 3) & 1) * 16);

    auto fill = [&](uint32_t bufbase, int k0) {
        if (aF32) {
#pragma unroll
            for (int i = tid; i < 512; i += 256) {
                int row = i >> 3, seg = i & 7;
                uint32_t so = AF_OFF + (uint32_t)(row * AF_RS + seg * 16);
                int ra = mBase + row; if (ra > M - 1) ra = M - 1;
                const float* src = (ra < splitRow)
                    ? ((const float*)Ahi + (size_t)ra * K)
                    : ((const float*)Alo + (size_t)(ra - splitRow) * K);
                cp16(bufbase + so, src + k0 + seg * 4);
            }
        } else {
            int row = tid >> 2, seg = tid & 3;
            uint32_t so = (uint32_t)(row * RS_B + seg * 16);
            int ra = mBase + row; if (ra > M - 1) ra = M - 1;
            size_t ea = (size_t)ra * K + k0 + seg * 8;
            cp16(bufbase + so,       Ahi + ea);
            cp16(bufbase + A_B + so, Alo + ea);
        }
#pragma unroll
        for (int i = tid; i < 512; i += 256) {
            int row = i >> 2, seg = i & 3;
            uint32_t so = (uint32_t)(row * RS_B + seg * 16);
            size_t eb = (size_t)(nBase + row) * K + k0 + seg * 8;
            cp16(bufbase + 2 * A_B + so,       Bhi + eb);
            cp16(bufbase + 2 * A_B + B_B + so, Blo + eb);
        }
    };

    fill(sb, 0);
    CP_COMMIT();

    for (int c = 0; c < nchunk; c++) {
        if (c + 1 < nchunk) {
            fill(sb + ((c + 1) & 1) * STG, (c + 1) << 5);
            CP_COMMIT();
            CP_WAIT1();
        } else {
            CP_WAIT0();
        }
        __syncthreads();

        const uint32_t rel = (uint32_t)(c & 1) * STG;
        if (aF32) {
            int row = tid >> 2, g4 = tid & 3;
            const char* fp = smem + rel + AF_OFF + row * AF_RS + g4 * 32;
            float4 va = *(const float4*)fp;
            float4 vb = *(const float4*)(fp + 16);
            uint32_t hi[4], lo[4];
            hi[0] = pack_bf2(va.x, va.y);
            hi[1] = pack_bf2(va.z, va.w);
            hi[2] = pack_bf2(vb.x, vb.y);
            hi[3] = pack_bf2(vb.z, vb.w);
            lo[0] = pack_bf2(va.x - __bfloat162float(((__nv_bfloat162*)&hi[0])->x),
                             va.y - __bfloat162float(((__nv_bfloat162*)&hi[0])->y));
            lo[1] = pack_bf2(va.z - __bfloat162float(((__nv_bfloat162*)&hi[1])->x),
                             va.w - __bfloat162float(((__nv_bfloat162*)&hi[1])->y));
            lo[2] = pack_bf2(vb.x - __bfloat162float(((__nv_bfloat162*)&hi[2])->x),
                             vb.y - __bfloat162float(((__nv_bfloat162*)&hi[2])->y));
            lo[3] = pack_bf2(vb.z - __bfloat162float(((__nv_bfloat162*)&hi[3])->x),
                             vb.w - __bfloat162float(((__nv_bfloat162*)&hi[3])->y));
            *(uint4*)(smem + rel + row * RS_B + g4 * 16)       = make_uint4(hi[0], hi[1], hi[2], hi[3]);
            *(uint4*)(smem + rel + A_B + row * RS_B + g4 * 16) = make_uint4(lo[0], lo[1], lo[2], lo[3]);
            __syncthreads();
        }

        const uint32_t sbuf = sb + rel;
        const uint32_t aB = sbuf + aOff;
        const uint32_t bB = sbuf + bOff;

#pragma unroll
        for (int ks = 0; ks < 2; ks++) {
            const uint32_t ko = ks * 32;
            uint32_t ah[MT][4], al[MT][4], bh[4][2], bl[4][2];
#pragma unroll
            for (int mt = 0; mt < MT; mt++) {
                ldsm4(ah[mt], aB + mt * (16 * RS_B) + ko);
                ldsm4(al[mt], aB + A_B + mt * (16 * RS_B) + ko);
            }
#pragma unroll
            for (int p = 0; p < 2; p++) {
                uint32_t r[4];
                ldsm4(r, bB + p * (16 * RS_B) + ko);
                bh[2 * p][0] = r[0]; bh[2 * p][1] = r[1];
                bh[2 * p + 1][0] = r[2]; bh[2 * p + 1][1] = r[3];
                ldsm4(r, bB + B_B + p * (16 * RS_B) + ko);
                bl[2 * p][0] = r[0]; bl[2 * p][1] = r[1];
                bl[2 * p + 1][0] = r[2]; bl[2 * p + 1][1] = r[3];
            }
#pragma unroll
            for (int mt = 0; mt < MT; mt++)
#pragma unroll
                for (int nt = 0; nt < 4; nt++) {
                    mma_bf16(acc[mt][nt], ah[mt][0], ah[mt][1], ah[mt][2], ah[mt][3], bh[nt][0], bh[nt][1]);
                    mma_bf16(acc[mt][nt], ah[mt][0], ah[mt][1], ah[mt][2], ah[mt][3], bl[nt][0], bl[nt][1]);
                    mma_bf16(acc[mt][nt], al[mt][0], al[mt][1], al[mt][2], al[mt][3], bh[nt][0], bh[nt][1]);
                }
        }
        __syncthreads();
    }

    // epilogue (+ optional fused attention dot partials)
    float* sA = (float*)smem;
    float* sD = sA + 4 * BM;
    const int hh = blockIdx.x;

#pragma unroll
    for (int mt = 0; mt < MT; mt++) {
#pragma unroll
        for (int half = 0; half < 2; half++) {
            const int lrow = wrow + mt * 16 + gid + half * 8;
            const int row = mBase + lrow;
            float ps = 0.f, pd = 0.f;
#pragma unroll
            for (int nt = 0; nt < 4; nt++) {
                const int cl = wcol + nt * 8 + tig * 2;
                const int col = nBase + cl;
                float v0 = acc[mt][nt][half * 2 + 0];
                float v1 = acc[mt][nt][half * 2 + 1];
                if (bias) { v0 += bias[col]; v1 += bias[col + 1]; }
                if (attS) {
                    ps += v0 * attS[hh * 128 + cl] + v1 * attS[hh * 128 + cl + 1];
                    pd += v0 * attD[hh * 128 + cl] + v1 * attD[hh * 128 + cl + 1];
                }
                if (row < M) {
                    size_t oi = (size_t)row * Nc + col;
                    if (Cf && row >= splitRow) *(float2*)(Cf + oi) = make_float2(v0, v1);
                    if (Chi && row < splitRow) {
                        __nv_bfloat162 h, l;
                        h.x = __float2bfloat16(v0); l.x = __float2bfloat16(v0 - __bfloat162float(h.x));
                        h.y = __float2bfloat16(v1); l.y = __float2bfloat16(v1 - __bfloat162float(h.y));
                        *(__nv_bfloat162*)(Chi + oi) = h;
                        *(__nv_bfloat162*)(Clo + oi) = l;
                    }
                }
            }
            if (attS) {
                ps += __shfl_xor_sync(0xffffffffu, ps, 1);
                ps += __shfl_xor_sync(0xffffffffu, ps, 2);
                pd += __shfl_xor_sync(0xffffffffu, pd, 1);
                pd += __shfl_xor_sync(0xffffffffu, pd, 2);
                if (tig == 0) {
                    sA[(wid >> 1) * BM + lrow] = ps;
                    sD[(wid >> 1) * BM + lrow] = pd;
                }
            }
        }
    }
    if (attS) {
        __syncthreads();
        if (tid < BM) {
            int row = mBase + tid;
            if (row < M) {
                int H = Nc >> 7;
                outS[row * H + hh] = sA[tid] + sA[BM + tid] + sA[2 * BM + tid] + sA[3 * BM + tid];
                outD[row * H + hh] = sD[tid] + sD[BM + tid] + sD[2 * BM + tid] + sD[3 * BM + tid];
            }
        }
    }
}

__device__ __forceinline__ float lrelu(float e) { return e > 0.f ? e : 0.2f * e; }

// ---------------- GAT1 agg: single-pass softmax + bias + ELU + bf16 split out ----------------
__global__ void k_agg1(const float* __restrict__ hpre, const float* __restrict__ as_,
                       const float* __restrict__ ad_, const float* __restrict__ bias,
                       __nv_bfloat16* __restrict__ ohi, __nv_bfloat16* __restrict__ olo) {
    int gw = (blockIdx.x * blockDim.x + threadIdx.x) >> 5;
    int lane = threadIdx.x & 31;
    if (gw >= NN * HEADS) return;
    int n = gw / HEADS, hh = gw - n * HEADS;
    int beg = g_off[n], end = g_off[n + 1];
    float adn = ad_[gw];

    float ws = 0.f;
    float4 acc = make_float4(0.f, 0.f, 0.f, 0.f);
    const float4* h4 = (const float4*)hpre;
    for (int i = beg; i < end; i++) {
        int s = g_csr[i];
        float ex = __expf(lrelu(as_[s * HEADS + hh] + adn));
        ws += ex;
        float4 v = h4[(size_t)(s * HEADS + hh) * 32 + lane];
        acc.x += ex * v.x; acc.y += ex * v.y; acc.z += ex * v.z; acc.w += ex * v.w;
    }
    float inv = 1.f / (ws + 1e-16f);
    float4 b = ((const float4*)bias)[hh * 32 + lane];
    float4 o;
    o.x = acc.x * inv + b.x; o.y = acc.y * inv + b.y;
    o.z = acc.z * inv + b.z; o.w = acc.w * inv + b.w;
    o.x = o.x > 0.f ? o.x : expm1f(o.x);
    o.y = o.y > 0.f ? o.y : expm1f(o.y);
    o.z = o.z > 0.f ? o.z : expm1f(o.z);
    o.w = o.w > 0.f ? o.w : expm1f(o.w);
    size_t oi = (size_t)gw * 128 + lane * 4;
    __nv_bfloat162 h01, h23, l01, l23;
    h01.x = __float2bfloat16(o.x); l01.x = __float2bfloat16(o.x - __bfloat162float(h01.x));
    h01.y = __float2bfloat16(o.y); l01.y = __float2bfloat16(o.y - __bfloat162float(h01.y));
    h23.x = __float2bfloat16(o.z); l23.x = __float2bfloat16(o.z - __bfloat162float(h23.x));
    h23.y = __float2bfloat16(o.w); l23.y = __float2bfloat16(o.w - __bfloat162float(h23.y));
    *(__nv_bfloat162*)(ohi + oi) = h01; *(__nv_bfloat162*)(ohi + oi + 2) = h23;
    *(__nv_bfloat162*)(olo + oi) = l01; *(__nv_bfloat162*)(olo + oi + 2) = l23;
}

// ---------------- GAT2 agg: single-pass softmax + bias + beta*gp + bf16 split out ----------------
__global__ void k_agg2(const float* __restrict__ hpre, const float* __restrict__ as_,
                       const float* __restrict__ ad_, const float* __restrict__ bias,
                       const float* __restrict__ gp, const float* __restrict__ beta,
                       __nv_bfloat16* __restrict__ ohi, __nv_bfloat16* __restrict__ olo) {
    int n = (blockIdx.x * blockDim.x + threadIdx.x) >> 5;
    int lane = threadIdx.x & 31;
    if (n >= NN) return;
    int beg = g_off[n], end = g_off[n + 1];
    float adn = ad_[n];

    float ws = 0.f;
    float4 acc = make_float4(0.f, 0.f, 0.f, 0.f);
    const float4* h4 = (const float4*)hpre;
    for (int i = beg; i < end; i++) {
        int s = g_csr[i];
        float ex = __expf(lrelu(as_[s] + adn));
        ws += ex;
        float4 v = h4[(size_t)s * 32 + lane];
        acc.x += ex * v.x; acc.y += ex * v.y; acc.z += ex * v.z; acc.w += ex * v.w;
    }
    float inv = 1.f / (ws + 1e-16f);
    float bt = *beta;
    float4 b = ((const float4*)bias)[lane];
    float4 gv = ((const float4*)gp)[(size_t)n * 32 + lane];
    float4 o;
    o.x = acc.x * inv + b.x + bt * gv.x;
    o.y = acc.y * inv + b.y + bt * gv.y;
    o.z = acc.z * inv + b.z + bt * gv.z;
    o.w = acc.w * inv + b.w + bt * gv.w;
    size_t oi = (size_t)n * 128 + lane * 4;
    __nv_bfloat162 h01, h23, l01, l23;
    h01.x = __float2bfloat16(o.x); l01.x = __float2bfloat16(o.x - __bfloat162float(h01.x));
    h01.y = __float2bfloat16(o.y); l01.y = __float2bfloat16(o.y - __bfloat162float(h01.y));
    h23.x = __float2bfloat16(o.z); l23.x = __float2bfloat16(o.z - __bfloat162float(h23.x));
    h23.y = __float2bfloat16(o.w); l23.y = __float2bfloat16(o.w - __bfloat162float(h23.y));
    *(__nv_bfloat162*)(ohi + oi) = h01; *(__nv_bfloat162*)(ohi + oi + 2) = h23;
    *(__nv_bfloat162*)(olo + oi) = l01; *(__nv_bfloat162*)(olo + oi + 2) = l23;
}

// ---------------- launch ----------------
extern "C" void kernel_launch(void* const* d_in, const int* in_sizes, int n_in,
                              void* d_out, int out_size) {
    const float* x      = (const float*)d_in[0];
    const int*   ei     = (const int*)  d_in[1];
    const float* g      = (const float*)d_in[2];
    const float* proj_W = (const float*)d_in[3];
    const float* proj_b = (const float*)d_in[4];
    const float* g1_W   = (const float*)d_in[5];
    const float* g1_as  = (const float*)d_in[6];
    const float* g1_ad  = (const float*)d_in[7];
    const float* g1_b   = (const float*)d_in[8];
    const float* g2_W   = (const float*)d_in[9];
    const float* g2_as  = (const float*)d_in[10];
    const float* g2_ad  = (const float*)d_in[11];
    const float* g2_b   = (const float*)d_in[12];
    const float* dec_W  = (const float*)d_in[13];
    const float* dec_b  = (const float*)d_in[14];
    const float* beta   = (const float*)d_in[15];
    float* out = (float*)d_out;

    __nv_bfloat16 *xpgp_hi, *xpgp_lo, *h1_hi, *h1_lo, *h2_hi, *h2_lo;
    __nv_bfloat16 *wp_hi, *wp_lo, *w1_hi, *w1_lo, *w2_hi, *w2_lo, *wd_hi, *wd_lo;
    float *xpgp, *h1pre, *h2pre, *as1, *ad1, *as2, *ad2;
    int* degp;
    cudaGetSymbolAddress((void**)&xpgp,    g_xpgp);
    cudaGetSymbolAddress((void**)&xpgp_hi, g_xpgp_hi); cudaGetSymbolAddress((void**)&xpgp_lo, g_xpgp_lo);
    cudaGetSymbolAddress((void**)&h1pre,   g_h1pre);
    cudaGetSymbolAddress((void**)&h1_hi,   g_h1_hi);   cudaGetSymbolAddress((void**)&h1_lo,   g_h1_lo);
    cudaGetSymbolAddress((void**)&h2pre,   g_h2pre);
    cudaGetSymbolAddress((void**)&h2_hi,   g_h2_hi);   cudaGetSymbolAddress((void**)&h2_lo,   g_h2_lo);
    cudaGetSymbolAddress((void**)&wp_hi,   g_wp_hi);   cudaGetSymbolAddress((void**)&wp_lo,   g_wp_lo);
    cudaGetSymbolAddress((void**)&w1_hi,   g_w1_hi);   cudaGetSymbolAddress((void**)&w1_lo,   g_w1_lo);
    cudaGetSymbolAddress((void**)&w2_hi,   g_w2_hi);   cudaGetSymbolAddress((void**)&w2_lo,   g_w2_lo);
    cudaGetSymbolAddress((void**)&wd_hi,   g_wd_hi);   cudaGetSymbolAddress((void**)&wd_lo,   g_wd_lo);
    cudaGetSymbolAddress((void**)&as1, g_as1); cudaGetSymbolAddress((void**)&ad1, g_ad1);
    cudaGetSymbolAddress((void**)&as2, g_as2); cudaGetSymbolAddress((void**)&ad2, g_ad2);
    cudaGetSymbolAddress((void**)&degp, g_deg);

    cudaFuncSetAttribute(k_gemm_mma, cudaFuncAttributeMaxDynamicSharedMemorySize, GSMEM);

    // prep: deg=0 (memset) -> weight split + edge count -> scan -> fill
    cudaMemsetAsync(degp, 0, NN * sizeof(int));
    k_wsplitall<<<(WS1 + WS2 + WS3 + WS4 + 255) / 256, 256>>>(
        proj_W, g1_W, g2_W, dec_W, ei, wp_hi, wp_lo, w1_hi, w1_lo, w2_hi, w2_lo, wd_hi, wd_lo);
    k_scan<<<1, 1024>>>();
    k_fill<<<(TE + 255) / 256, 256>>>(ei);

    // proj (batched x|g, fp32 A direct): rows<NN -> hi/lo (GAT1 input), rows>=NN -> f32 (gp)
    k_gemm_mma<<<dim3(1, (MP + BM - 1) / BM), 256, GSMEM>>>(
        (const __nv_bfloat16*)x, (const __nv_bfloat16*)g, wp_hi, wp_lo, proj_b,
        xpgp, xpgp_hi, xpgp_lo,
        nullptr, nullptr, nullptr, nullptr, MP, DIN, DH, NN, 1);

    // GAT1: [10000,128] @ [128,512] + fused attention dots
    k_gemm_mma<<<dim3(HEADS * DH / 128, (NN + BM - 1) / BM), 256, GSMEM>>>(
        xpgp_hi, xpgp_lo, w1_hi, w1_lo, nullptr, h1pre, nullptr, nullptr,
        g1_as, g1_ad, as1, ad1, NN, DH, HEADS * DH, 0, 0);
    k_agg1<<<(NN * HEADS * 32 + 255) / 256, 256>>>(h1pre, as1, ad1, g1_b, h1_hi, h1_lo);

    // GAT2: [10000,512] @ [512,128] + fused attention dots
    k_gemm_mma<<<dim3(1, (NN + BM - 1) / BM), 256, GSMEM>>>(
        h1_hi, h1_lo, w2_hi, w2_lo, nullptr, h2pre, nullptr, nullptr,
        g2_as, g2_ad, as2, ad2, NN, HEADS * DH, DH, 0, 0);
    k_agg2<<<(NN * 32 + 255) / 256, 256>>>(h2pre, as2, ad2, g2_b, xpgp + (size_t)NN * DH, beta, h2_hi, h2_lo);

    // decoder: [10000,128] @ [128,768]
    k_gemm_mma<<<dim3(DIN / 128, (NN + BM - 1) / BM), 256, GSMEM>>>(
        h2_hi, h2_lo, wd_hi, wd_lo, dec_b, out, nullptr, nullptr,
        nullptr, nullptr, nullptr, nullptr, NN, DH, DIN, 0, 0);
}

// round 15
// speedup vs baseline: 1.1515x; 1.0281x over previous
#include <cuda_runtime.h>
#include <cuda_bf16.h>
#include <cstdint>

#define NN    10000
#define EE    160000
#define TE    (EE + NN)
#define DIN   768
#define DH    128
#define HEADS 4
#define MP    (2 * NN)           // batched proj rows (x then g)

// ---------------- scratch (static device globals) ----------------
__device__ __align__(256) float         g_xpgp[MP * DH];
__device__ __align__(256) __nv_bfloat16 g_xpgp_hi[MP * DH], g_xpgp_lo[MP * DH];
__device__ __align__(256) float         g_h1pre[NN * HEADS * DH];
__device__ __align__(256) __nv_bfloat16 g_h1_hi[NN * HEADS * DH], g_h1_lo[NN * HEADS * DH];
__device__ __align__(256) float         g_h2pre[NN * DH];
__device__ __align__(256) __nv_bfloat16 g_h2_hi[NN * DH], g_h2_lo[NN * DH];
// transposed + split weights: Bt[n][k]
__device__ __align__(256) __nv_bfloat16 g_wp_hi[DH * DIN],        g_wp_lo[DH * DIN];
__device__ __align__(256) __nv_bfloat16 g_w1_hi[HEADS * DH * DH], g_w1_lo[HEADS * DH * DH];
__device__ __align__(256) __nv_bfloat16 g_w2_hi[DH * HEADS * DH], g_w2_lo[DH * HEADS * DH];
__device__ __align__(256) __nv_bfloat16 g_wd_hi[DIN * DH],        g_wd_lo[DIN * DH];
__device__ float g_as1[NN * HEADS], g_ad1[NN * HEADS], g_as2[NN], g_ad2[NN];
__device__ int   g_deg[NN], g_off[NN + 1], g_cur[NN], g_csr[TE];

// ---------------- helpers ----------------
__device__ __forceinline__ uint32_t smem_u32(const void* p) {
    uint32_t a;
    asm("{ .reg .u64 t; cvta.to.shared.u64 t, %1; cvt.u32.u64 %0, t; }" : "=r"(a) : "l"(p));
    return a;
}
__device__ __forceinline__ void cp16(uint32_t dst, const void* src) {
    asm volatile("cp.async.cg.shared.global [%0], [%1], 16;" :: "r"(dst), "l"(src));
}
#define CP_COMMIT() asm volatile("cp.async.commit_group;" ::: "memory")
#define CP_WAIT1()  asm volatile("cp.async.wait_group 1;" ::: "memory")
#define CP_WAIT0()  asm volatile("cp.async.wait_group 0;" ::: "memory")

__device__ __forceinline__ void mma_bf16(float* c, uint32_t a0, uint32_t a1, uint32_t a2, uint32_t a3,
                                         uint32_t b0, uint32_t b1) {
    asm volatile("mma.sync.aligned.m16n8k16.row.col.f32.bf16.bf16.f32 "
                 "{%0,%1,%2,%3}, {%4,%5,%6,%7}, {%8,%9}, {%0,%1,%2,%3};"
                 : "+f"(c[0]), "+f"(c[1]), "+f"(c[2]), "+f"(c[3])
                 : "r"(a0), "r"(a1), "r"(a2), "r"(a3), "r"(b0), "r"(b1));
}
__device__ __forceinline__ void ldsm4(uint32_t* r, uint32_t addr) {
    asm volatile("ldmatrix.sync.aligned.m8n8.x4.shared.b16 {%0,%1,%2,%3}, [%4];"
                 : "=r"(r[0]), "=r"(r[1]), "=r"(r[2]), "=r"(r[3]) : "r"(addr));
}
__device__ __forceinline__ uint32_t pack_bf2(float a, float b) {
    __nv_bfloat162 p;
    p.x = __float2bfloat16(a);
    p.y = __float2bfloat16(b);
    return *(uint32_t*)&p;
}

// ---------------- fused weight transpose+split + edge degree count ----------------
// g_deg zeroed by cudaMemsetAsync BEFORE this kernel.
#define WS1 (DIN * DH)
#define WS2 (DH * HEADS * DH)
#define WS3 (HEADS * DH * DH)
#define WS4 (DH * DIN)
__global__ void k_wsplitall(const float* __restrict__ Wp, const float* __restrict__ W1,
                            const float* __restrict__ W2, const float* __restrict__ Wd,
                            const int* __restrict__ ei,
                            __nv_bfloat16* __restrict__ wph, __nv_bfloat16* __restrict__ wpl,
                            __nv_bfloat16* __restrict__ w1h, __nv_bfloat16* __restrict__ w1l,
                            __nv_bfloat16* __restrict__ w2h, __nv_bfloat16* __restrict__ w2l,
                            __nv_bfloat16* __restrict__ wdh, __nv_bfloat16* __restrict__ wdl) {
    int i = blockIdx.x * blockDim.x + threadIdx.x;
    if (i < EE) atomicAdd(&g_deg[ei[EE + i]], 1);
    const float* W; __nv_bfloat16 *bh, *bl; int K, N, j;
    if (i < WS1)                         { W = Wp; bh = wph; bl = wpl; K = DIN; N = DH;         j = i; }
    else if (i < WS1 + WS2)              { W = W1; bh = w1h; bl = w1l; K = DH;  N = HEADS * DH; j = i - WS1; }
    else if (i < WS1 + WS2 + WS3)        { W = W2; bh = w2h; bl = w2l; K = HEADS * DH; N = DH;  j = i - WS1 - WS2; }
    else if (i < WS1 + WS2 + WS3 + WS4)  { W = Wd; bh = wdh; bl = wdl; K = DH;  N = DIN;        j = i - WS1 - WS2 - WS3; }
    else return;
    int k = j / N, n = j - k * N;
    float v = W[j];
    __nv_bfloat16 h = __float2bfloat16(v);
    bh[(size_t)n * K + k] = h;
    bl[(size_t)n * K + k] = __float2bfloat16(v - __bfloat162float(h));
}

// ---------------- CSR scan + fill ----------------
__global__ void k_scan() {
    __shared__ int wsum[32];
    const int CH = 10;
    int tid = threadIdx.x, lane = tid & 31, wid = tid >> 5;
    int base = tid * CH;
    int pref[CH];
    int s = 0;
#pragma unroll
    for (int j = 0; j < CH; j++) {
        int idx = base + j;
        pref[j] = (idx < NN) ? g_deg[idx] + 1 : 0;
        s += pref[j];
    }
    int sc = s;
#pragma unroll
    for (int o = 1; o < 32; o <<= 1) {
        int t = __shfl_up_sync(0xffffffffu, sc, o);
        if (lane >= o) sc += t;
    }
    if (lane == 31) wsum[wid] = sc;
    __syncthreads();
    if (wid == 0) {
        int w = wsum[lane];
#pragma unroll
        for (int o = 1; o < 32; o <<= 1) {
            int t = __shfl_up_sync(0xffffffffu, w, o);
            if (lane >= o) w += t;
        }
        wsum[lane] = w;
    }
    __syncthreads();
    int run = sc - s + (wid ? wsum[wid - 1] : 0);
#pragma unroll
    for (int j = 0; j < CH; j++) {
        int idx = base + j;
        if (idx < NN) { g_off[idx] = run; g_cur[idx] = run; run += pref[j]; }
    }
    if (tid == 1023) g_off[NN] = run;
}
__global__ void k_fill(const int* __restrict__ ei) {
    int i = blockIdx.x * blockDim.x + threadIdx.x;
    if (i < EE) {
        int d = ei[EE + i];
        g_csr[atomicAdd(&g_cur[d], 1)] = ei[i];
    } else if (i < TE) {
        int n = i - EE;
        g_csr[atomicAdd(&g_cur[n], 1)] = n;
    }
}

// ---------------- mma.sync bf16x3 GEMM (BM=64, 2-stage) ----------------
// AF32=0: A pre-split bf16 (Ahi/Alo) via cp.async; occ 3.
// AF32=1: Ahi=x(f32), Alo=g(f32), rows>=splitRow from g; LDG-prefetch regs ->
//         convert -> STS into the SAME Ah/Al stage layout (bit-identical values); occ 2.
#define RS_B   80
#define B_B    10240
#define BM     64
#define A_B    (BM * RS_B)                 // 5120
#define STG    (2 * A_B + 2 * B_B)         // 30720
#define GSMEM  (2 * STG)                   // 61440

template <int AF32>
__global__ __launch_bounds__(256, AF32 ? 2 : 3) void k_gemm_mma(
    const __nv_bfloat16* __restrict__ Ahi, const __nv_bfloat16* __restrict__ Alo,
    const __nv_bfloat16* __restrict__ Bhi, const __nv_bfloat16* __restrict__ Blo,
    const float* __restrict__ bias,
    float* __restrict__ Cf, __nv_bfloat16* __restrict__ Chi, __nv_bfloat16* __restrict__ Clo,
    const float* __restrict__ attS, const float* __restrict__ attD,
    float* __restrict__ outS, float* __restrict__ outD,
    int M, int K, int Nc, int splitRow)
{
    constexpr int MT = 2;
    extern __shared__ char smem[];
    const uint32_t sb = smem_u32(smem);
    const int tid = threadIdx.x, wid = tid >> 5, lane = tid & 31;
    const int gid = lane >> 2, tig = lane & 3;
    const int mBase = blockIdx.y * BM, nBase = blockIdx.x * 128;
    const int wrow = (wid & 1) * 32, wcol = (wid >> 1) * 32;

    float acc[MT][4][4];
#pragma unroll
    for (int i = 0; i < MT; i++)
#pragma unroll
        for (int j = 0; j < 4; j++)
#pragma unroll
            for (int q = 0; q < 4; q++) acc[i][j][q] = 0.f;

    const int nchunk = K >> 5;
    const uint32_t aOff = (uint32_t)((wrow + (lane & 15)) * RS_B + (lane >> 4) * 16);
    const uint32_t bOff = (uint32_t)(2 * A_B + (wcol + ((lane >> 4) << 3) + (lane & 7)) * RS_B
                                     + ((lane >> 3) & 1) * 16);

    // fp32-A prefetch state (AF32 only): thread covers row=tid>>2, floats [g4*8, g4*8+8)
    const int arow = tid >> 2, ag4 = tid & 3;
    const float* asrc = nullptr;
    float4 pfa, pfb;
    if (AF32) {
        int ra = mBase + arow; if (ra > M - 1) ra = M - 1;
        asrc = (ra < splitRow) ? ((const float*)Ahi + (size_t)ra * K)
                               : ((const float*)Alo + (size_t)(ra - splitRow) * K);
        pfa = *(const float4*)(asrc + ag4 * 8);
        pfb = *(const float4*)(asrc + ag4 * 8 + 4);
    }

    auto fillA = [&](uint32_t bufbase, int k0) {    // bf16 path only
        int row = tid >> 2, seg = tid & 3;
        uint32_t so = (uint32_t)(row * RS_B + seg * 16);
        int ra = mBase + row; if (ra > M - 1) ra = M - 1;
        size_t ea = (size_t)ra * K + k0 + seg * 8;
        cp16(bufbase + so,       Ahi + ea);
        cp16(bufbase + A_B + so, Alo + ea);
    };
    auto fillB = [&](uint32_t bufbase, int k0) {
#pragma unroll
        for (int i = tid; i < 512; i += 256) {
            int row = i >> 2, seg = i & 3;
            uint32_t so = (uint32_t)(row * RS_B + seg * 16);
            size_t eb = (size_t)(nBase + row) * K + k0 + seg * 8;
            cp16(bufbase + 2 * A_B + so,       Bhi + eb);
            cp16(bufbase + 2 * A_B + B_B + so, Blo + eb);
        }
    };

    if (!AF32) fillA(sb, 0);
    fillB(sb, 0);
    CP_COMMIT();

    for (int c = 0; c < nchunk; c++) {
        const uint32_t rel = (uint32_t)(c & 1) * STG;

        if (AF32) {
            // STS chunk c from prefetched regs (same values as pre-split path).
            // Stage (c&1) A-region last read by compute c-2, fenced by its bottom sync.
            uint32_t hi[4], lo[4];
            hi[0] = pack_bf2(pfa.x, pfa.y);
            hi[1] = pack_bf2(pfa.z, pfa.w);
            hi[2] = pack_bf2(pfb.x, pfb.y);
            hi[3] = pack_bf2(pfb.z, pfb.w);
            lo[0] = pack_bf2(pfa.x - __bfloat162float(((__nv_bfloat162*)&hi[0])->x),
                             pfa.y - __bfloat162float(((__nv_bfloat162*)&hi[0])->y));
            lo[1] = pack_bf2(pfa.z - __bfloat162float(((__nv_bfloat162*)&hi[1])->x),
                             pfa.w - __bfloat162float(((__nv_bfloat162*)&hi[1])->y));
            lo[2] = pack_bf2(pfb.x - __bfloat162float(((__nv_bfloat162*)&hi[2])->x),
                             pfb.y - __bfloat162float(((__nv_bfloat162*)&hi[2])->y));
            lo[3] = pack_bf2(pfb.z - __bfloat162float(((__nv_bfloat162*)&hi[3])->x),
                             pfb.w - __bfloat162float(((__nv_bfloat162*)&hi[3])->y));
            *(uint4*)(smem + rel + arow * RS_B + ag4 * 16)       = make_uint4(hi[0], hi[1], hi[2], hi[3]);
            *(uint4*)(smem + rel + A_B + arow * RS_B + ag4 * 16) = make_uint4(lo[0], lo[1], lo[2], lo[3]);
        }

        if (c + 1 < nchunk) {
            const uint32_t nrel = (uint32_t)((c + 1) & 1) * STG;
            if (!AF32) fillA(sb + nrel, (c + 1) << 5);
            fillB(sb + nrel, (c + 1) << 5);
            CP_COMMIT();
            if (AF32) {    // LDG chunk c+1; latency hidden behind compute of chunk c
                const int k0 = (c + 1) << 5;
                pfa = *(const float4*)(asrc + k0 + ag4 * 8);
                pfb = *(const float4*)(asrc + k0 + ag4 * 8 + 4);
            }
            CP_WAIT1();
        } else {
            CP_WAIT0();
        }
        __syncthreads();

        const uint32_t sbuf = sb + rel;
        const uint32_t aB = sbuf + aOff;
        const uint32_t bB = sbuf + bOff;

#pragma unroll
        for (int ks = 0; ks < 2; ks++) {
            const uint32_t ko = ks * 32;
            uint32_t ah[MT][4], al[MT][4], bh[4][2], bl[4][2];
#pragma unroll
            for (int mt = 0; mt < MT; mt++) {
                ldsm4(ah[mt], aB + mt * (16 * RS_B) + ko);
                ldsm4(al[mt], aB + A_B + mt * (16 * RS_B) + ko);
            }
#pragma unroll
            for (int p = 0; p < 2; p++) {
                uint32_t r[4];
                ldsm4(r, bB + p * (16 * RS_B) + ko);
                bh[2 * p][0] = r[0]; bh[2 * p][1] = r[1];
                bh[2 * p + 1][0] = r[2]; bh[2 * p + 1][1] = r[3];
                ldsm4(r, bB + B_B + p * (16 * RS_B) + ko);
                bl[2 * p][0] = r[0]; bl[2 * p][1] = r[1];
                bl[2 * p + 1][0] = r[2]; bl[2 * p + 1][1] = r[3];
            }
#pragma unroll
            for (int mt = 0; mt < MT; mt++)
#pragma unroll
                for (int nt = 0; nt < 4; nt++) {
                    mma_bf16(acc[mt][nt], ah[mt][0], ah[mt][1], ah[mt][2], ah[mt][3], bh[nt][0], bh[nt][1]);
                    mma_bf16(acc[mt][nt], ah[mt][0], ah[mt][1], ah[mt][2], ah[mt][3], bl[nt][0], bl[nt][1]);
                    mma_bf16(acc[mt][nt], al[mt][0], al[mt][1], al[mt][2], al[mt][3], bh[nt][0], bh[nt][1]);
                }
        }
        __syncthreads();
    }

    // epilogue (+ optional fused attention dot partials)
    float* sA = (float*)smem;
    float* sD = sA + 4 * BM;
    const int hh = blockIdx.x;

#pragma unroll
    for (int mt = 0; mt < MT; mt++) {
#pragma unroll
        for (int half = 0; half < 2; half++) {
            const int lrow = wrow + mt * 16 + gid + half * 8;
            const int row = mBase + lrow;
            float ps = 0.f, pd = 0.f;
#pragma unroll
            for (int nt = 0; nt < 4; nt++) {
                const int cl = wcol + nt * 8 + tig * 2;
                const int col = nBase + cl;
                float v0 = acc[mt][nt][half * 2 + 0];
                float v1 = acc[mt][nt][half * 2 + 1];
                if (bias) { v0 += bias[col]; v1 += bias[col + 1]; }
                if (attS) {
                    ps += v0 * attS[hh * 128 + cl] + v1 * attS[hh * 128 + cl + 1];
                    pd += v0 * attD[hh * 128 + cl] + v1 * attD[hh * 128 + cl + 1];
                }
                if (row < M) {
                    size_t oi = (size_t)row * Nc + col;
                    if (Cf && row >= splitRow) *(float2*)(Cf + oi) = make_float2(v0, v1);
                    if (Chi && row < splitRow) {
                        __nv_bfloat162 h, l;
                        h.x = __float2bfloat16(v0); l.x = __float2bfloat16(v0 - __bfloat162float(h.x));
                        h.y = __float2bfloat16(v1); l.y = __float2bfloat16(v1 - __bfloat162float(h.y));
                        *(__nv_bfloat162*)(Chi + oi) = h;
                        *(__nv_bfloat162*)(Clo + oi) = l;
                    }
                }
            }
            if (attS) {
                ps += __shfl_xor_sync(0xffffffffu, ps, 1);
                ps += __shfl_xor_sync(0xffffffffu, ps, 2);
                pd += __shfl_xor_sync(0xffffffffu, pd, 1);
                pd += __shfl_xor_sync(0xffffffffu, pd, 2);
                if (tig == 0) {
                    sA[(wid >> 1) * BM + lrow] = ps;
                    sD[(wid >> 1) * BM + lrow] = pd;
                }
            }
        }
    }
    if (attS) {
        __syncthreads();
        if (tid < BM) {
            int row = mBase + tid;
            if (row < M) {
                int H = Nc >> 7;
                outS[row * H + hh] = sA[tid] + sA[BM + tid] + sA[2 * BM + tid] + sA[3 * BM + tid];
                outD[row * H + hh] = sD[tid] + sD[BM + tid] + sD[2 * BM + tid] + sD[3 * BM + tid];
            }
        }
    }
}

__device__ __forceinline__ float lrelu(float e) { return e > 0.f ? e : 0.2f * e; }

// ---------------- GAT1 agg: single-pass softmax + bias + ELU + bf16 split out ----------------
__global__ void k_agg1(const float* __restrict__ hpre, const float* __restrict__ as_,
                       const float* __restrict__ ad_, const float* __restrict__ bias,
                       __nv_bfloat16* __restrict__ ohi, __nv_bfloat16* __restrict__ olo) {
    int gw = (blockIdx.x * blockDim.x + threadIdx.x) >> 5;
    int lane = threadIdx.x & 31;
    if (gw >= NN * HEADS) return;
    int n = gw / HEADS, hh = gw - n * HEADS;
    int beg = g_off[n], end = g_off[n + 1];
    float adn = ad_[gw];

    float ws = 0.f;
    float4 acc = make_float4(0.f, 0.f, 0.f, 0.f);
    const float4* h4 = (const float4*)hpre;
    for (int i = beg; i < end; i++) {
        int s = g_csr[i];
        float ex = __expf(lrelu(as_[s * HEADS + hh] + adn));
        ws += ex;
        float4 v = h4[(size_t)(s * HEADS + hh) * 32 + lane];
        acc.x += ex * v.x; acc.y += ex * v.y; acc.z += ex * v.z; acc.w += ex * v.w;
    }
    float inv = 1.f / (ws + 1e-16f);
    float4 b = ((const float4*)bias)[hh * 32 + lane];
    float4 o;
    o.x = acc.x * inv + b.x; o.y = acc.y * inv + b.y;
    o.z = acc.z * inv + b.z; o.w = acc.w * inv + b.w;
    o.x = o.x > 0.f ? o.x : expm1f(o.x);
    o.y = o.y > 0.f ? o.y : expm1f(o.y);
    o.z = o.z > 0.f ? o.z : expm1f(o.z);
    o.w = o.w > 0.f ? o.w : expm1f(o.w);
    size_t oi = (size_t)gw * 128 + lane * 4;
    __nv_bfloat162 h01, h23, l01, l23;
    h01.x = __float2bfloat16(o.x); l01.x = __float2bfloat16(o.x - __bfloat162float(h01.x));
    h01.y = __float2bfloat16(o.y); l01.y = __float2bfloat16(o.y - __bfloat162float(h01.y));
    h23.x = __float2bfloat16(o.z); l23.x = __float2bfloat16(o.z - __bfloat162float(h23.x));
    h23.y = __float2bfloat16(o.w); l23.y = __float2bfloat16(o.w - __bfloat162float(h23.y));
    *(__nv_bfloat162*)(ohi + oi) = h01; *(__nv_bfloat162*)(ohi + oi + 2) = h23;
    *(__nv_bfloat162*)(olo + oi) = l01; *(__nv_bfloat162*)(olo + oi + 2) = l23;
}

// ---------------- GAT2 agg: single-pass softmax + bias + beta*gp + bf16 split out ----------------
__global__ void k_agg2(const float* __restrict__ hpre, const float* __restrict__ as_,
                       const float* __restrict__ ad_, const float* __restrict__ bias,
                       const float* __restrict__ gp, const float* __restrict__ beta,
                       __nv_bfloat16* __restrict__ ohi, __nv_bfloat16* __restrict__ olo) {
    int n = (blockIdx.x * blockDim.x + threadIdx.x) >> 5;
    int lane = threadIdx.x & 31;
    if (n >= NN) return;
    int beg = g_off[n], end = g_off[n + 1];
    float adn = ad_[n];

    float ws = 0.f;
    float4 acc = make_float4(0.f, 0.f, 0.f, 0.f);
    const float4* h4 = (const float4*)hpre;
    for (int i = beg; i < end; i++) {
        int s = g_csr[i];
        float ex = __expf(lrelu(as_[s] + adn));
        ws += ex;
        float4 v = h4[(size_t)s * 32 + lane];
        acc.x += ex * v.x; acc.y += ex * v.y; acc.z += ex * v.z; acc.w += ex * v.w;
    }
    float inv = 1.f / (ws + 1e-16f);
    float bt = *beta;
    float4 b = ((const float4*)bias)[lane];
    float4 gv = ((const float4*)gp)[(size_t)n * 32 + lane];
    float4 o;
    o.x = acc.x * inv + b.x + bt * gv.x;
    o.y = acc.y * inv + b.y + bt * gv.y;
    o.z = acc.z * inv + b.z + bt * gv.z;
    o.w = acc.w * inv + b.w + bt * gv.w;
    size_t oi = (size_t)n * 128 + lane * 4;
    __nv_bfloat162 h01, h23, l01, l23;
    h01.x = __float2bfloat16(o.x); l01.x = __float2bfloat16(o.x - __bfloat162float(h01.x));
    h01.y = __float2bfloat16(o.y); l01.y = __float2bfloat16(o.y - __bfloat162float(h01.y));
    h23.x = __float2bfloat16(o.z); l23.x = __float2bfloat16(o.z - __bfloat162float(h23.x));
    h23.y = __float2bfloat16(o.w); l23.y = __float2bfloat16(o.w - __bfloat162float(h23.y));
    *(__nv_bfloat162*)(ohi + oi) = h01; *(__nv_bfloat162*)(ohi + oi + 2) = h23;
    *(__nv_bfloat162*)(olo + oi) = l01; *(__nv_bfloat162*)(olo + oi + 2) = l23;
}

// ---------------- launch ----------------
extern "C" void kernel_launch(void* const* d_in, const int* in_sizes, int n_in,
                              void* d_out, int out_size) {
    const float* x      = (const float*)d_in[0];
    const int*   ei     = (const int*)  d_in[1];
    const float* g      = (const float*)d_in[2];
    const float* proj_W = (const float*)d_in[3];
    const float* proj_b = (const float*)d_in[4];
    const float* g1_W   = (const float*)d_in[5];
    const float* g1_as  = (const float*)d_in[6];
    const float* g1_ad  = (const float*)d_in[7];
    const float* g1_b   = (const float*)d_in[8];
    const float* g2_W   = (const float*)d_in[9];
    const float* g2_as  = (const float*)d_in[10];
    const float* g2_ad  = (const float*)d_in[11];
    const float* g2_b   = (const float*)d_in[12];
    const float* dec_W  = (const float*)d_in[13];
    const float* dec_b  = (const float*)d_in[14];
    const float* beta   = (const float*)d_in[15];
    float* out = (float*)d_out;

    __nv_bfloat16 *xpgp_hi, *xpgp_lo, *h1_hi, *h1_lo, *h2_hi, *h2_lo;
    __nv_bfloat16 *wp_hi, *wp_lo, *w1_hi, *w1_lo, *w2_hi, *w2_lo, *wd_hi, *wd_lo;
    float *xpgp, *h1pre, *h2pre, *as1, *ad1, *as2, *ad2;
    int* degp;
    cudaGetSymbolAddress((void**)&xpgp,    g_xpgp);
    cudaGetSymbolAddress((void**)&xpgp_hi, g_xpgp_hi); cudaGetSymbolAddress((void**)&xpgp_lo, g_xpgp_lo);
    cudaGetSymbolAddress((void**)&h1pre,   g_h1pre);
    cudaGetSymbolAddress((void**)&h1_hi,   g_h1_hi);   cudaGetSymbolAddress((void**)&h1_lo,   g_h1_lo);
    cudaGetSymbolAddress((void**)&h2pre,   g_h2pre);
    cudaGetSymbolAddress((void**)&h2_hi,   g_h2_hi);   cudaGetSymbolAddress((void**)&h2_lo,   g_h2_lo);
    cudaGetSymbolAddress((void**)&wp_hi,   g_wp_hi);   cudaGetSymbolAddress((void**)&wp_lo,   g_wp_lo);
    cudaGetSymbolAddress((void**)&w1_hi,   g_w1_hi);   cudaGetSymbolAddress((void**)&w1_lo,   g_w1_lo);
    cudaGetSymbolAddress((void**)&w2_hi,   g_w2_hi);   cudaGetSymbolAddress((void**)&w2_lo,   g_w2_lo);
    cudaGetSymbolAddress((void**)&wd_hi,   g_wd_hi);   cudaGetSymbolAddress((void**)&wd_lo,   g_wd_lo);
    cudaGetSymbolAddress((void**)&as1, g_as1); cudaGetSymbolAddress((void**)&ad1, g_ad1);
    cudaGetSymbolAddress((void**)&as2, g_as2); cudaGetSymbolAddress((void**)&ad2, g_ad2);
    cudaGetSymbolAddress((void**)&degp, g_deg);

    cudaFuncSetAttribute(k_gemm_mma<0>, cudaFuncAttributeMaxDynamicSharedMemorySize, GSMEM);
    cudaFuncSetAttribute(k_gemm_mma<1>, cudaFuncAttributeMaxDynamicSharedMemorySize, GSMEM);

    // prep: deg=0 (memset) -> weight split + edge count -> scan -> fill
    cudaMemsetAsync(degp, 0, NN * sizeof(int));
    k_wsplitall<<<(WS1 + WS2 + WS3 + WS4 + 255) / 256, 256>>>(
        proj_W, g1_W, g2_W, dec_W, ei, wp_hi, wp_lo, w1_hi, w1_lo, w2_hi, w2_lo, wd_hi, wd_lo);
    k_scan<<<1, 1024>>>();
    k_fill<<<(TE + 255) / 256, 256>>>(ei);

    // proj (batched x|g, fp32 A via LDG-prefetch): rows<NN -> hi/lo, rows>=NN -> f32 (gp)
    k_gemm_mma<1><<<dim3(1, (MP + BM - 1) / BM), 256, GSMEM>>>(
        (const __nv_bfloat16*)x, (const __nv_bfloat16*)g, wp_hi, wp_lo, proj_b,
        xpgp, xpgp_hi, xpgp_lo,
        nullptr, nullptr, nullptr, nullptr, MP, DIN, DH, NN);

    // GAT1: [10000,128] @ [128,512] + fused attention dots
    k_gemm_mma<0><<<dim3(HEADS * DH / 128, (NN + BM - 1) / BM), 256, GSMEM>>>(
        xpgp_hi, xpgp_lo, w1_hi, w1_lo, nullptr, h1pre, nullptr, nullptr,
        g1_as, g1_ad, as1, ad1, NN, DH, HEADS * DH, 0);
    k_agg1<<<(NN * HEADS * 32 + 255) / 256, 256>>>(h1pre, as1, ad1, g1_b, h1_hi, h1_lo);

    // GAT2: [10000,512] @ [512,128] + fused attention dots
    k_gemm_mma<0><<<dim3(1, (NN + BM - 1) / BM), 256, GSMEM>>>(
        h1_hi, h1_lo, w2_hi, w2_lo, nullptr, h2pre, nullptr, nullptr,
        g2_as, g2_ad, as2, ad2, NN, HEADS * DH, DH, 0);
    k_agg2<<<(NN * 32 + 255) / 256, 256>>>(h2pre, as2, ad2, g2_b, xpgp + (size_t)NN * DH, beta, h2_hi, h2_lo);

    // decoder: [10000,128] @ [128,768]
    k_gemm_mma<0><<<dim3(DIN / 128, (NN + BM - 1) / BM), 256, GSMEM>>>(
        h2_hi, h2_lo, wd_hi, wd_lo, dec_b, out, nullptr, nullptr,
        nullptr, nullptr, nullptr, nullptr, NN, DH, DIN, 0);
}

// round 16
// speedup vs baseline: 1.1738x; 1.0194x over previous
#include <cuda_runtime.h>
#include <cuda_bf16.h>
#include <cstdint>

#define NN    10000
#define EE    160000
#define TE    (EE + NN)
#define DIN   768
#define DH    128
#define HEADS 4
#define MP    (2 * NN)           // batched proj rows (x then g)

// ---------------- scratch (static device globals) ----------------
__device__ __align__(256) float         g_xpgp[MP * DH];
__device__ __align__(256) __nv_bfloat16 g_xpgp_hi[MP * DH], g_xpgp_lo[MP * DH];
__device__ __align__(256) float         g_h1pre[NN * HEADS * DH];
__device__ __align__(256) __nv_bfloat16 g_h1_hi[NN * HEADS * DH], g_h1_lo[NN * HEADS * DH];
__device__ __align__(256) float         g_h2pre[NN * DH];
__device__ __align__(256) __nv_bfloat16 g_h2_hi[NN * DH], g_h2_lo[NN * DH];
// transposed + split weights: Bt[n][k]
__device__ __align__(256) __nv_bfloat16 g_wp_hi[DH * DIN],        g_wp_lo[DH * DIN];
__device__ __align__(256) __nv_bfloat16 g_w1_hi[HEADS * DH * DH], g_w1_lo[HEADS * DH * DH];
__device__ __align__(256) __nv_bfloat16 g_w2_hi[DH * HEADS * DH], g_w2_lo[DH * HEADS * DH];
__device__ __align__(256) __nv_bfloat16 g_wd_hi[DIN * DH],        g_wd_lo[DIN * DH];
__device__ float g_as1[NN * HEADS], g_ad1[NN * HEADS], g_as2[NN], g_ad2[NN];
__device__ int   g_deg[NN], g_off[NN + 1], g_cur[NN], g_csr[TE];

// ---------------- helpers ----------------
__device__ __forceinline__ uint32_t smem_u32(const void* p) {
    uint32_t a;
    asm("{ .reg .u64 t; cvta.to.shared.u64 t, %1; cvt.u32.u64 %0, t; }" : "=r"(a) : "l"(p));
    return a;
}
__device__ __forceinline__ void cp16(uint32_t dst, const void* src) {
    asm volatile("cp.async.cg.shared.global [%0], [%1], 16;" :: "r"(dst), "l"(src));
}
#define CP_COMMIT() asm volatile("cp.async.commit_group;" ::: "memory")
#define CP_WAIT1()  asm volatile("cp.async.wait_group 1;" ::: "memory")
#define CP_WAIT0()  asm volatile("cp.async.wait_group 0;" ::: "memory")

__device__ __forceinline__ void mma_bf16(float* c, uint32_t a0, uint32_t a1, uint32_t a2, uint32_t a3,
                                         uint32_t b0, uint32_t b1) {
    asm volatile("mma.sync.aligned.m16n8k16.row.col.f32.bf16.bf16.f32 "
                 "{%0,%1,%2,%3}, {%4,%5,%6,%7}, {%8,%9}, {%0,%1,%2,%3};"
                 : "+f"(c[0]), "+f"(c[1]), "+f"(c[2]), "+f"(c[3])
                 : "r"(a0), "r"(a1), "r"(a2), "r"(a3), "r"(b0), "r"(b1));
}
__device__ __forceinline__ void ldsm4(uint32_t* r, uint32_t addr) {
    asm volatile("ldmatrix.sync.aligned.m8n8.x4.shared.b16 {%0,%1,%2,%3}, [%4];"
                 : "=r"(r[0]), "=r"(r[1]), "=r"(r[2]), "=r"(r[3]) : "r"(addr));
}
__device__ __forceinline__ uint32_t pack_bf2(float a, float b) {
    __nv_bfloat162 p;
    p.x = __float2bfloat16(a);
    p.y = __float2bfloat16(b);
    return *(uint32_t*)&p;
}

// ---------------- fused weight transpose+split + edge degree count ----------------
// g_deg zeroed by cudaMemsetAsync BEFORE this kernel.
#define WS1 (DIN * DH)
#define WS2 (DH * HEADS * DH)
#define WS3 (HEADS * DH * DH)
#define WS4 (DH * DIN)
__global__ void k_wsplitall(const float* __restrict__ Wp, const float* __restrict__ W1,
                            const float* __restrict__ W2, const float* __restrict__ Wd,
                            const int* __restrict__ ei,
                            __nv_bfloat16* __restrict__ wph, __nv_bfloat16* __restrict__ wpl,
                            __nv_bfloat16* __restrict__ w1h, __nv_bfloat16* __restrict__ w1l,
                            __nv_bfloat16* __restrict__ w2h, __nv_bfloat16* __restrict__ w2l,
                            __nv_bfloat16* __restrict__ wdh, __nv_bfloat16* __restrict__ wdl) {
    int i = blockIdx.x * blockDim.x + threadIdx.x;
    if (i < EE) atomicAdd(&g_deg[ei[EE + i]], 1);
    const float* W; __nv_bfloat16 *bh, *bl; int K, N, j;
    if (i < WS1)                         { W = Wp; bh = wph; bl = wpl; K = DIN; N = DH;         j = i; }
    else if (i < WS1 + WS2)              { W = W1; bh = w1h; bl = w1l; K = DH;  N = HEADS * DH; j = i - WS1; }
    else if (i < WS1 + WS2 + WS3)        { W = W2; bh = w2h; bl = w2l; K = HEADS * DH; N = DH;  j = i - WS1 - WS2; }
    else if (i < WS1 + WS2 + WS3 + WS4)  { W = Wd; bh = wdh; bl = wdl; K = DH;  N = DIN;        j = i - WS1 - WS2 - WS3; }
    else return;
    int k = j / N, n = j - k * N;
    float v = W[j];
    __nv_bfloat16 h = __float2bfloat16(v);
    bh[(size_t)n * K + k] = h;
    bl[(size_t)n * K + k] = __float2bfloat16(v - __bfloat162float(h));
}

// ---------------- CSR scan + fill ----------------
__global__ void k_scan() {
    __shared__ int wsum[32];
    const int CH = 10;
    int tid = threadIdx.x, lane = tid & 31, wid = tid >> 5;
    int base = tid * CH;
    int pref[CH];
    int s = 0;
#pragma unroll
    for (int j = 0; j < CH; j++) {
        int idx = base + j;
        pref[j] = (idx < NN) ? g_deg[idx] + 1 : 0;
        s += pref[j];
    }
    int sc = s;
#pragma unroll
    for (int o = 1; o < 32; o <<= 1) {
        int t = __shfl_up_sync(0xffffffffu, sc, o);
        if (lane >= o) sc += t;
    }
    if (lane == 31) wsum[wid] = sc;
    __syncthreads();
    if (wid == 0) {
        int w = wsum[lane];
#pragma unroll
        for (int o = 1; o < 32; o <<= 1) {
            int t = __shfl_up_sync(0xffffffffu, w, o);
            if (lane >= o) w += t;
        }
        wsum[lane] = w;
    }
    __syncthreads();
    int run = sc - s + (wid ? wsum[wid - 1] : 0);
#pragma unroll
    for (int j = 0; j < CH; j++) {
        int idx = base + j;
        if (idx < NN) { g_off[idx] = run; g_cur[idx] = run; run += pref[j]; }
    }
    if (tid == 1023) g_off[NN] = run;
}
__global__ void k_fill(const int* __restrict__ ei) {
    int i = blockIdx.x * blockDim.x + threadIdx.x;
    if (i < EE) {
        int d = ei[EE + i];
        g_csr[atomicAdd(&g_cur[d], 1)] = ei[i];
    } else if (i < TE) {
        int n = i - EE;
        g_csr[atomicAdd(&g_cur[n], 1)] = n;
    }
}

// ---------------- mma.sync bf16x3 GEMM (BM=64, 2-stage) ----------------
// AF32=0: A pre-split bf16 via cp.async. AF32=1: fp32 A (x|g) via LDG-prefetch ->
//         convert -> STS into the same Ah/Al stage layout (bit-identical values).
// ATT=1 compiles the fused attention-dot epilogue; ATT=0 strips it (regs).
#define RS_B   80
#define B_B    10240
#define BM     64
#define A_B    (BM * RS_B)                 // 5120
#define STG    (2 * A_B + 2 * B_B)         // 30720
#define GSMEM  (2 * STG)                   // 61440

template <int AF32, int ATT>
__global__ __launch_bounds__(256, 3) void k_gemm_mma(
    const __nv_bfloat16* __restrict__ Ahi, const __nv_bfloat16* __restrict__ Alo,
    const __nv_bfloat16* __restrict__ Bhi, const __nv_bfloat16* __restrict__ Blo,
    const float* __restrict__ bias,
    float* __restrict__ Cf, __nv_bfloat16* __restrict__ Chi, __nv_bfloat16* __restrict__ Clo,
    const float* __restrict__ attS, const float* __restrict__ attD,
    float* __restrict__ outS, float* __restrict__ outD,
    int M, int K, int Nc, int splitRow)
{
    constexpr int MT = 2;
    extern __shared__ char smem[];
    const uint32_t sb = smem_u32(smem);
    const int tid = threadIdx.x, wid = tid >> 5, lane = tid & 31;
    const int gid = lane >> 2, tig = lane & 3;
    const int mBase = blockIdx.y * BM, nBase = blockIdx.x * 128;
    const int wrow = (wid & 1) * 32, wcol = (wid >> 1) * 32;

    float acc[MT][4][4];
#pragma unroll
    for (int i = 0; i < MT; i++)
#pragma unroll
        for (int j = 0; j < 4; j++)
#pragma unroll
            for (int q = 0; q < 4; q++) acc[i][j][q] = 0.f;

    const int nchunk = K >> 5;
    const uint32_t aOff = (uint32_t)((wrow + (lane & 15)) * RS_B + (lane >> 4) * 16);
    const uint32_t bOff = (uint32_t)(2 * A_B + (wcol + ((lane >> 4) << 3) + (lane & 7)) * RS_B
                                     + ((lane >> 3) & 1) * 16);

    // fp32-A prefetch state (AF32 only)
    const int arow = tid >> 2, ag4 = tid & 3;
    const float* asrc = nullptr;
    float4 pfa, pfb;
    if (AF32) {
        int ra = mBase + arow; if (ra > M - 1) ra = M - 1;
        asrc = (ra < splitRow) ? ((const float*)Ahi + (size_t)ra * K)
                               : ((const float*)Alo + (size_t)(ra - splitRow) * K);
        pfa = *(const float4*)(asrc + ag4 * 8);
        pfb = *(const float4*)(asrc + ag4 * 8 + 4);
    }

    auto fillA = [&](uint32_t bufbase, int k0) {    // bf16 path only
        int row = tid >> 2, seg = tid & 3;
        uint32_t so = (uint32_t)(row * RS_B + seg * 16);
        int ra = mBase + row; if (ra > M - 1) ra = M - 1;
        size_t ea = (size_t)ra * K + k0 + seg * 8;
        cp16(bufbase + so,       Ahi + ea);
        cp16(bufbase + A_B + so, Alo + ea);
    };
    auto fillB = [&](uint32_t bufbase, int k0) {
#pragma unroll
        for (int i = tid; i < 512; i += 256) {
            int row = i >> 2, seg = i & 3;
            uint32_t so = (uint32_t)(row * RS_B + seg * 16);
            size_t eb = (size_t)(nBase + row) * K + k0 + seg * 8;
            cp16(bufbase + 2 * A_B + so,       Bhi + eb);
            cp16(bufbase + 2 * A_B + B_B + so, Blo + eb);
        }
    };

    if (!AF32) fillA(sb, 0);
    fillB(sb, 0);
    CP_COMMIT();

    for (int c = 0; c < nchunk; c++) {
        const uint32_t rel = (uint32_t)(c & 1) * STG;

        if (AF32) {
            uint32_t hi[4], lo[4];
            hi[0] = pack_bf2(pfa.x, pfa.y);
            hi[1] = pack_bf2(pfa.z, pfa.w);
            hi[2] = pack_bf2(pfb.x, pfb.y);
            hi[3] = pack_bf2(pfb.z, pfb.w);
            lo[0] = pack_bf2(pfa.x - __bfloat162float(((__nv_bfloat162*)&hi[0])->x),
                             pfa.y - __bfloat162float(((__nv_bfloat162*)&hi[0])->y));
            lo[1] = pack_bf2(pfa.z - __bfloat162float(((__nv_bfloat162*)&hi[1])->x),
                             pfa.w - __bfloat162float(((__nv_bfloat162*)&hi[1])->y));
            lo[2] = pack_bf2(pfb.x - __bfloat162float(((__nv_bfloat162*)&hi[2])->x),
                             pfb.y - __bfloat162float(((__nv_bfloat162*)&hi[2])->y));
            lo[3] = pack_bf2(pfb.z - __bfloat162float(((__nv_bfloat162*)&hi[3])->x),
                             pfb.w - __bfloat162float(((__nv_bfloat162*)&hi[3])->y));
            *(uint4*)(smem + rel + arow * RS_B + ag4 * 16)       = make_uint4(hi[0], hi[1], hi[2], hi[3]);
            *(uint4*)(smem + rel + A_B + arow * RS_B + ag4 * 16) = make_uint4(lo[0], lo[1], lo[2], lo[3]);
        }

        if (c + 1 < nchunk) {
            const uint32_t nrel = (uint32_t)((c + 1) & 1) * STG;
            if (!AF32) fillA(sb + nrel, (c + 1) << 5);
            fillB(sb + nrel, (c + 1) << 5);
            CP_COMMIT();
            if (AF32) {
                const int k0 = (c + 1) << 5;
                pfa = *(const float4*)(asrc + k0 + ag4 * 8);
                pfb = *(const float4*)(asrc + k0 + ag4 * 8 + 4);
            }
            CP_WAIT1();
        } else {
            CP_WAIT0();
        }
        __syncthreads();

        const uint32_t sbuf = sb + rel;
        const uint32_t aB = sbuf + aOff;
        const uint32_t bB = sbuf + bOff;

#pragma unroll
        for (int ks = 0; ks < 2; ks++) {
            const uint32_t ko = ks * 32;
            uint32_t ah[MT][4], al[MT][4], bh[4][2], bl[4][2];
#pragma unroll
            for (int mt = 0; mt < MT; mt++) {
                ldsm4(ah[mt], aB + mt * (16 * RS_B) + ko);
                ldsm4(al[mt], aB + A_B + mt * (16 * RS_B) + ko);
            }
#pragma unroll
            for (int p = 0; p < 2; p++) {
                uint32_t r[4];
                ldsm4(r, bB + p * (16 * RS_B) + ko);
                bh[2 * p][0] = r[0]; bh[2 * p][1] = r[1];
                bh[2 * p + 1][0] = r[2]; bh[2 * p + 1][1] = r[3];
                ldsm4(r, bB + B_B + p * (16 * RS_B) + ko);
                bl[2 * p][0] = r[0]; bl[2 * p][1] = r[1];
                bl[2 * p + 1][0] = r[2]; bl[2 * p + 1][1] = r[3];
            }
#pragma unroll
            for (int mt = 0; mt < MT; mt++)
#pragma unroll
                for (int nt = 0; nt < 4; nt++) {
                    mma_bf16(acc[mt][nt], ah[mt][0], ah[mt][1], ah[mt][2], ah[mt][3], bh[nt][0], bh[nt][1]);
                    mma_bf16(acc[mt][nt], ah[mt][0], ah[mt][1], ah[mt][2], ah[mt][3], bl[nt][0], bl[nt][1]);
                    mma_bf16(acc[mt][nt], al[mt][0], al[mt][1], al[mt][2], al[mt][3], bh[nt][0], bh[nt][1]);
                }
        }
        __syncthreads();
    }

    // epilogue (+ optional fused attention dot partials, compiled only when ATT=1)
    float* sA = (float*)smem;
    float* sD = sA + 4 * BM;
    const int hh = blockIdx.x;

#pragma unroll
    for (int mt = 0; mt < MT; mt++) {
#pragma unroll
        for (int half = 0; half < 2; half++) {
            const int lrow = wrow + mt * 16 + gid + half * 8;
            const int row = mBase + lrow;
            float ps = 0.f, pd = 0.f;
#pragma unroll
            for (int nt = 0; nt < 4; nt++) {
                const int cl = wcol + nt * 8 + tig * 2;
                const int col = nBase + cl;
                float v0 = acc[mt][nt][half * 2 + 0];
                float v1 = acc[mt][nt][half * 2 + 1];
                if (bias) { v0 += bias[col]; v1 += bias[col + 1]; }
                if (ATT) {
                    ps += v0 * attS[hh * 128 + cl] + v1 * attS[hh * 128 + cl + 1];
                    pd += v0 * attD[hh * 128 + cl] + v1 * attD[hh * 128 + cl + 1];
                }
                if (row < M) {
                    size_t oi = (size_t)row * Nc + col;
                    if (Cf && row >= splitRow) *(float2*)(Cf + oi) = make_float2(v0, v1);
                    if (Chi && row < splitRow) {
                        __nv_bfloat162 h, l;
                        h.x = __float2bfloat16(v0); l.x = __float2bfloat16(v0 - __bfloat162float(h.x));
                        h.y = __float2bfloat16(v1); l.y = __float2bfloat16(v1 - __bfloat162float(h.y));
                        *(__nv_bfloat162*)(Chi + oi) = h;
                        *(__nv_bfloat162*)(Clo + oi) = l;
                    }
                }
            }
            if (ATT) {
                ps += __shfl_xor_sync(0xffffffffu, ps, 1);
                ps += __shfl_xor_sync(0xffffffffu, ps, 2);
                pd += __shfl_xor_sync(0xffffffffu, pd, 1);
                pd += __shfl_xor_sync(0xffffffffu, pd, 2);
                if (tig == 0) {
                    sA[(wid >> 1) * BM + lrow] = ps;
                    sD[(wid >> 1) * BM + lrow] = pd;
                }
            }
        }
    }
    if (ATT) {
        __syncthreads();
        if (tid < BM) {
            int row = mBase + tid;
            if (row < M) {
                int H = Nc >> 7;
                outS[row * H + hh] = sA[tid] + sA[BM + tid] + sA[2 * BM + tid] + sA[3 * BM + tid];
                outD[row * H + hh] = sD[tid] + sD[BM + tid] + sD[2 * BM + tid] + sD[3 * BM + tid];
            }
        }
    }
}

__device__ __forceinline__ float lrelu(float e) { return e > 0.f ? e : 0.2f * e; }

// ---------------- GAT1 agg: single-pass softmax + bias + ELU + bf16 split out ----------------
__global__ void k_agg1(const float* __restrict__ hpre, const float* __restrict__ as_,
                       const float* __restrict__ ad_, const float* __restrict__ bias,
                       __nv_bfloat16* __restrict__ ohi, __nv_bfloat16* __restrict__ olo) {
    int gw = (blockIdx.x * blockDim.x + threadIdx.x) >> 5;
    int lane = threadIdx.x & 31;
    if (gw >= NN * HEADS) return;
    int n = gw / HEADS, hh = gw - n * HEADS;
    int beg = g_off[n], end = g_off[n + 1];
    float adn = ad_[gw];

    float ws = 0.f;
    float4 acc = make_float4(0.f, 0.f, 0.f, 0.f);
    const float4* h4 = (const float4*)hpre;
    for (int i = beg; i < end; i++) {
        int s = g_csr[i];
        float ex = __expf(lrelu(as_[s * HEADS + hh] + adn));
        ws += ex;
        float4 v = h4[(size_t)(s * HEADS + hh) * 32 + lane];
        acc.x += ex * v.x; acc.y += ex * v.y; acc.z += ex * v.z; acc.w += ex * v.w;
    }
    float inv = 1.f / (ws + 1e-16f);
    float4 b = ((const float4*)bias)[hh * 32 + lane];
    float4 o;
    o.x = acc.x * inv + b.x; o.y = acc.y * inv + b.y;
    o.z = acc.z * inv + b.z; o.w = acc.w * inv + b.w;
    o.x = o.x > 0.f ? o.x : expm1f(o.x);
    o.y = o.y > 0.f ? o.y : expm1f(o.y);
    o.z = o.z > 0.f ? o.z : expm1f(o.z);
    o.w = o.w > 0.f ? o.w : expm1f(o.w);
    size_t oi = (size_t)gw * 128 + lane * 4;
    __nv_bfloat162 h01, h23, l01, l23;
    h01.x = __float2bfloat16(o.x); l01.x = __float2bfloat16(o.x - __bfloat162float(h01.x));
    h01.y = __float2bfloat16(o.y); l01.y = __float2bfloat16(o.y - __bfloat162float(h01.y));
    h23.x = __float2bfloat16(o.z); l23.x = __float2bfloat16(o.z - __bfloat162float(h23.x));
    h23.y = __float2bfloat16(o.w); l23.y = __float2bfloat16(o.w - __bfloat162float(h23.y));
    *(__nv_bfloat162*)(ohi + oi) = h01; *(__nv_bfloat162*)(ohi + oi + 2) = h23;
    *(__nv_bfloat162*)(olo + oi) = l01; *(__nv_bfloat162*)(olo + oi + 2) = l23;
}

// ---------------- GAT2 agg: single-pass softmax + bias + beta*gp + bf16 split out ----------------
__global__ void k_agg2(const float* __restrict__ hpre, const float* __restrict__ as_,
                       const float* __restrict__ ad_, const float* __restrict__ bias,
                       const float* __restrict__ gp, const float* __restrict__ beta,
                       __nv_bfloat16* __restrict__ ohi, __nv_bfloat16* __restrict__ olo) {
    int n = (blockIdx.x * blockDim.x + threadIdx.x) >> 5;
    int lane = threadIdx.x & 31;
    if (n >= NN) return;
    int beg = g_off[n], end = g_off[n + 1];
    float adn = ad_[n];

    float ws = 0.f;
    float4 acc = make_float4(0.f, 0.f, 0.f, 0.f);
    const float4* h4 = (const float4*)hpre;
    for (int i = beg; i < end; i++) {
        int s = g_csr[i];
        float ex = __expf(lrelu(as_[s] + adn));
        ws += ex;
        float4 v = h4[(size_t)s * 32 + lane];
        acc.x += ex * v.x; acc.y += ex * v.y; acc.z += ex * v.z; acc.w += ex * v.w;
    }
    float inv = 1.f / (ws + 1e-16f);
    float bt = *beta;
    float4 b = ((const float4*)bias)[lane];
    float4 gv = ((const float4*)gp)[(size_t)n * 32 + lane];
    float4 o;
    o.x = acc.x * inv + b.x + bt * gv.x;
    o.y = acc.y * inv + b.y + bt * gv.y;
    o.z = acc.z * inv + b.z + bt * gv.z;
    o.w = acc.w * inv + b.w + bt * gv.w;
    size_t oi = (size_t)n * 128 + lane * 4;
    __nv_bfloat162 h01, h23, l01, l23;
    h01.x = __float2bfloat16(o.x); l01.x = __float2bfloat16(o.x - __bfloat162float(h01.x));
    h01.y = __float2bfloat16(o.y); l01.y = __float2bfloat16(o.y - __bfloat162float(h01.y));
    h23.x = __float2bfloat16(o.z); l23.x = __float2bfloat16(o.z - __bfloat162float(h23.x));
    h23.y = __float2bfloat16(o.w); l23.y = __float2bfloat16(o.w - __bfloat162float(h23.y));
    *(__nv_bfloat162*)(ohi + oi) = h01; *(__nv_bfloat162*)(ohi + oi + 2) = h23;
    *(__nv_bfloat162*)(olo + oi) = l01; *(__nv_bfloat162*)(olo + oi + 2) = l23;
}

// ---------------- launch ----------------
extern "C" void kernel_launch(void* const* d_in, const int* in_sizes, int n_in,
                              void* d_out, int out_size) {
    const float* x      = (const float*)d_in[0];
    const int*   ei     = (const int*)  d_in[1];
    const float* g      = (const float*)d_in[2];
    const float* proj_W = (const float*)d_in[3];
    const float* proj_b = (const float*)d_in[4];
    const float* g1_W   = (const float*)d_in[5];
    const float* g1_as  = (const float*)d_in[6];
    const float* g1_ad  = (const float*)d_in[7];
    const float* g1_b   = (const float*)d_in[8];
    const float* g2_W   = (const float*)d_in[9];
    const float* g2_as  = (const float*)d_in[10];
    const float* g2_ad  = (const float*)d_in[11];
    const float* g2_b   = (const float*)d_in[12];
    const float* dec_W  = (const float*)d_in[13];
    const float* dec_b  = (const float*)d_in[14];
    const float* beta   = (const float*)d_in[15];
    float* out = (float*)d_out;

    __nv_bfloat16 *xpgp_hi, *xpgp_lo, *h1_hi, *h1_lo, *h2_hi, *h2_lo;
    __nv_bfloat16 *wp_hi, *wp_lo, *w1_hi, *w1_lo, *w2_hi, *w2_lo, *wd_hi, *wd_lo;
    float *xpgp, *h1pre, *h2pre, *as1, *ad1, *as2, *ad2;
    int* degp;
    cudaGetSymbolAddress((void**)&xpgp,    g_xpgp);
    cudaGetSymbolAddress((void**)&xpgp_hi, g_xpgp_hi); cudaGetSymbolAddress((void**)&xpgp_lo, g_xpgp_lo);
    cudaGetSymbolAddress((void**)&h1pre,   g_h1pre);
    cudaGetSymbolAddress((void**)&h1_hi,   g_h1_hi);   cudaGetSymbolAddress((void**)&h1_lo,   g_h1_lo);
    cudaGetSymbolAddress((void**)&h2pre,   g_h2pre);
    cudaGetSymbolAddress((void**)&h2_hi,   g_h2_hi);   cudaGetSymbolAddress((void**)&h2_lo,   g_h2_lo);
    cudaGetSymbolAddress((void**)&wp_hi,   g_wp_hi);   cudaGetSymbolAddress((void**)&wp_lo,   g_wp_lo);
    cudaGetSymbolAddress((void**)&w1_hi,   g_w1_hi);   cudaGetSymbolAddress((void**)&w1_lo,   g_w1_lo);
    cudaGetSymbolAddress((void**)&w2_hi,   g_w2_hi);   cudaGetSymbolAddress((void**)&w2_lo,   g_w2_lo);
    cudaGetSymbolAddress((void**)&wd_hi,   g_wd_hi);   cudaGetSymbolAddress((void**)&wd_lo,   g_wd_lo);
    cudaGetSymbolAddress((void**)&as1, g_as1); cudaGetSymbolAddress((void**)&ad1, g_ad1);
    cudaGetSymbolAddress((void**)&as2, g_as2); cudaGetSymbolAddress((void**)&ad2, g_ad2);
    cudaGetSymbolAddress((void**)&degp, g_deg);

    cudaFuncSetAttribute(k_gemm_mma<0, 0>, cudaFuncAttributeMaxDynamicSharedMemorySize, GSMEM);
    cudaFuncSetAttribute(k_gemm_mma<0, 1>, cudaFuncAttributeMaxDynamicSharedMemorySize, GSMEM);
    cudaFuncSetAttribute(k_gemm_mma<1, 0>, cudaFuncAttributeMaxDynamicSharedMemorySize, GSMEM);

    // prep: deg=0 (memset) -> weight split + edge count -> scan -> fill
    cudaMemsetAsync(degp, 0, NN * sizeof(int));
    k_wsplitall<<<(WS1 + WS2 + WS3 + WS4 + 255) / 256, 256>>>(
        proj_W, g1_W, g2_W, dec_W, ei, wp_hi, wp_lo, w1_hi, w1_lo, w2_hi, w2_lo, wd_hi, wd_lo);
    k_scan<<<1, 1024>>>();
    k_fill<<<(TE + 255) / 256, 256>>>(ei);

    // proj (batched x|g, fp32 A via LDG-prefetch): rows<NN -> hi/lo, rows>=NN -> f32 (gp)
    k_gemm_mma<1, 0><<<dim3(1, (MP + BM - 1) / BM), 256, GSMEM>>>(
        (const __nv_bfloat16*)x, (const __nv_bfloat16*)g, wp_hi, wp_lo, proj_b,
        xpgp, xpgp_hi, xpgp_lo,
        nullptr, nullptr, nullptr, nullptr, MP, DIN, DH, NN);

    // GAT1: [10000,128] @ [128,512] + fused attention dots
    k_gemm_mma<0, 1><<<dim3(HEADS * DH / 128, (NN + BM - 1) / BM), 256, GSMEM>>>(
        xpgp_hi, xpgp_lo, w1_hi, w1_lo, nullptr, h1pre, nullptr, nullptr,
        g1_as, g1_ad, as1, ad1, NN, DH, HEADS * DH, 0);
    k_agg1<<<(NN * HEADS * 32 + 255) / 256, 256>>>(h1pre, as1, ad1, g1_b, h1_hi, h1_lo);

    // GAT2: [10000,512] @ [512,128] + fused attention dots
    k_gemm_mma<0, 1><<<dim3(1, (NN + BM - 1) / BM), 256, GSMEM>>>(
        h1_hi, h1_lo, w2_hi, w2_lo, nullptr, h2pre, nullptr, nullptr,
        g2_as, g2_ad, as2, ad2, NN, HEADS * DH, DH, 0);
    k_agg2<<<(NN * 32 + 255) / 256, 256>>>(h2pre, as2, ad2, g2_b, xpgp + (size_t)NN * DH, beta, h2_hi, h2_lo);

    // decoder: [10000,128] @ [128,768]
    k_gemm_mma<0, 0><<<dim3(DIN / 128, (NN + BM - 1) / BM), 256, GSMEM>>>(
        h2_hi, h2_lo, wd_hi, wd_lo, dec_b, out, nullptr, nullptr,
        nullptr, nullptr, nullptr, nullptr, NN, DH, DIN, 0);
}